// round 2
// baseline (speedup 1.0000x reference)
#include <cuda_runtime.h>
#include <math.h>
#include <stdint.h>

#define H       256
#define BSZ     256
#define TLEN    128
#define G4      1024
#define DIN     512
#define DSTATE  16
#define DTRANK  16

__device__ float g_wx[(size_t)2 * TLEN * BSZ * G4];
__device__ float g_out0[(size_t)BSZ * TLEN * 512];
__device__ float g_h[2 * BSZ * H];
__device__ float g_c[2 * BSZ * H];

__device__ __forceinline__ float sigmoidf_(float x) { return 1.0f / (1.0f + __expf(-x)); }

// ---------------- wx GEMM: wx[d][t][b][j] = sum_k in[b][ts][k] * W[d][j][k]
__global__ void wx_gemm_kernel(const float* __restrict__ Ain,
                               const float* __restrict__ W, int K)
{
    const int d  = blockIdx.z;
    const int n0 = blockIdx.x * 128;
    const int m0 = blockIdx.y * 128;
    const int tid = threadIdx.x;
    const int tx = tid & 15, ty = tid >> 4;

    __shared__ float As[16][132];
    __shared__ float Bs[16][132];

    const float* Wd = W + (size_t)d * G4 * K;
    float acc[8][8];
#pragma unroll
    for (int i = 0; i < 8; i++)
#pragma unroll
        for (int j = 0; j < 8; j++) acc[i][j] = 0.0f;

    const int lr = tid >> 1;
    const int lk = (tid & 1) * 4;
    const int mA = m0 + lr;
    const int tA = mA >> 8;
    const int bA = mA & 255;
    const int tsA = d ? (TLEN - 1 - tA) : tA;
    const float* arow = Ain + ((size_t)bA * TLEN + tsA) * K;
    const float* brow = Wd + (size_t)(n0 + lr) * K;

    for (int k0 = 0; k0 < K; k0 += 16) {
#pragma unroll
        for (int l = 0; l < 2; l++) {
            int kk = lk + l * 8;
            float4 a4 = *(const float4*)(arow + k0 + kk);
            As[kk + 0][lr] = a4.x; As[kk + 1][lr] = a4.y;
            As[kk + 2][lr] = a4.z; As[kk + 3][lr] = a4.w;
            float4 b4 = *(const float4*)(brow + k0 + kk);
            Bs[kk + 0][lr] = b4.x; Bs[kk + 1][lr] = b4.y;
            Bs[kk + 2][lr] = b4.z; Bs[kk + 3][lr] = b4.w;
        }
        __syncthreads();
#pragma unroll
        for (int kk = 0; kk < 16; kk++) {
            float av[8], bv[8];
            *(float4*)&av[0] = *(const float4*)&As[kk][ty * 8];
            *(float4*)&av[4] = *(const float4*)&As[kk][ty * 8 + 4];
            *(float4*)&bv[0] = *(const float4*)&Bs[kk][tx * 8];
            *(float4*)&bv[4] = *(const float4*)&Bs[kk][tx * 8 + 4];
#pragma unroll
            for (int i = 0; i < 8; i++)
#pragma unroll
                for (int j = 0; j < 8; j++) acc[i][j] += av[i] * bv[j];
        }
        __syncthreads();
    }
#pragma unroll
    for (int i = 0; i < 8; i++) {
        int m = m0 + ty * 8 + i;
        int t = m >> 8;
        int b = m & 255;
        float* orow = g_wx + (((size_t)d * TLEN + t) * BSZ + b) * G4 + n0 + tx * 8;
        *(float4*)(orow)     = make_float4(acc[i][0], acc[i][1], acc[i][2], acc[i][3]);
        *(float4*)(orow + 4) = make_float4(acc[i][4], acc[i][5], acc[i][6], acc[i][7]);
    }
}

// ---------------- persistent scan ----------------
struct ScanSmem {
    float sw[32 * 1025];
    float h[4][H];
    float c[4][H];
    float g[4][G4];
    float xm[4][DIN];
    float zs[4][DIN];
    float yv[4][DIN];
    float xdbl[4][48];
    float bsum[G4];
    float cw1[DIN], cb[DIN], dm[DIN], dtb[DIN];
    float bcs[4];
};

template<int NOJ>
__device__ __forceinline__ void mv_accum(ScanSmem* S, const float* __restrict__ Wg, int Kdim,
                                         const float* act, int actStride,
                                         float (&acc)[NOJ][4], int tid)
{
    for (int k0 = 0; k0 < Kdim; k0 += 32) {
        const int iters = NOJ * 8;
#pragma unroll
        for (int i = 0; i < iters; i++) {
            int j = (tid >> 3) + i * 32;
            int kk4 = (tid & 7) * 4;
            float4 w4 = *(const float4*)(Wg + (size_t)j * Kdim + k0 + kk4);
            S->sw[(kk4 + 0) * 1025 + j] = w4.x;
            S->sw[(kk4 + 1) * 1025 + j] = w4.y;
            S->sw[(kk4 + 2) * 1025 + j] = w4.z;
            S->sw[(kk4 + 3) * 1025 + j] = w4.w;
        }
        __syncthreads();
#pragma unroll 4
        for (int kk = 0; kk < 32; kk++) {
            float a0 = act[0 * actStride + k0 + kk];
            float a1 = act[1 * actStride + k0 + kk];
            float a2 = act[2 * actStride + k0 + kk];
            float a3 = act[3 * actStride + k0 + kk];
#pragma unroll
            for (int oj = 0; oj < NOJ; oj++) {
                float wv = S->sw[kk * 1025 + tid + oj * 256];
                acc[oj][0] += wv * a0;
                acc[oj][1] += wv * a1;
                acc[oj][2] += wv * a2;
                acc[oj][3] += wv * a3;
            }
        }
        __syncthreads();
    }
}

__global__ void scan_kernel(
    const float* __restrict__ whh,
    const float* __restrict__ bih,
    const float* __restrict__ bhh,
    const float* __restrict__ in_proj,
    const float* __restrict__ conv_w,
    const float* __restrict__ conv_b,
    const float* __restrict__ x_proj,
    const float* __restrict__ dt_w,
    const float* __restrict__ dt_b,
    const float* __restrict__ Dm,
    const float* __restrict__ out_proj,
    float* __restrict__ outbuf,
    int first_layer)
{
    extern __shared__ char smem_raw[];
    ScanSmem* S = (ScanSmem*)smem_raw;
    const int tid = threadIdx.x;
    const int d   = blockIdx.x >> 6;
    const int grp = blockIdx.x & 63;
    const int b0  = grp * 4;
    const float* whh_d = whh + (size_t)d * G4 * H;
    const int wid = tid >> 5, lane = tid & 31;

#pragma unroll
    for (int i = 0; i < 4; i++) {
        int j = tid + i * 256;
        S->bsum[j] = bih[d * G4 + j] + bhh[d * G4 + j];
    }
#pragma unroll
    for (int i = 0; i < 2; i++) {
        int j = tid + i * 256;
        S->cw1[j] = conv_w[j * 2 + 1];
        S->cb[j]  = conv_b[j];
        S->dm[j]  = Dm[j];
        S->dtb[j] = dt_b[j];
    }
#pragma unroll
    for (int r = 0; r < 4; r++) {
        if (first_layer) { S->h[r][tid] = 0.0f; S->c[r][tid] = 0.0f; }
        else {
            S->h[r][tid] = g_h[((size_t)d * BSZ + b0 + r) * H + tid];
            S->c[r][tid] = g_c[((size_t)d * BSZ + b0 + r) * H + tid];
        }
    }
    __syncthreads();

    for (int t = 0; t < TLEN; t++) {
        // A: g = wx_t + h @ Whh^T
        float acc[4][4];
#pragma unroll
        for (int oj = 0; oj < 4; oj++)
#pragma unroll
            for (int r = 0; r < 4; r++)
                acc[oj][r] = g_wx[(((size_t)d * TLEN + t) * BSZ + b0 + r) * G4 + tid + oj * 256];
        mv_accum<4>(S, whh_d, H, &S->h[0][0], H, acc, tid);
#pragma unroll
        for (int oj = 0; oj < 4; oj++)
#pragma unroll
            for (int r = 0; r < 4; r++)
                S->g[r][tid + oj * 256] = acc[oj][r];
        __syncthreads();

        // B: xz = u @ in_proj^T (u = g[:, :H]); silu paths
#pragma unroll
        for (int oj = 0; oj < 4; oj++)
#pragma unroll
            for (int r = 0; r < 4; r++) acc[oj][r] = 0.0f;
        mv_accum<4>(S, in_proj, H, &S->g[0][0], G4, acc, tid);
#pragma unroll
        for (int oj = 0; oj < 4; oj++) {
            int j = tid + oj * 256;
#pragma unroll
            for (int r = 0; r < 4; r++) {
                float v = acc[oj][r];
                if (j < DIN) {
                    float pre = v * S->cw1[j] + S->cb[j];
                    S->xm[r][j] = pre * sigmoidf_(pre);
                } else {
                    S->zs[r][j - DIN] = v * sigmoidf_(v);
                }
            }
        }
        __syncthreads();

        // C: x_dbl = xm @ x_proj^T (48 outputs)
        for (int o = wid; o < 48; o += 8) {
            const float* xr = x_proj + (size_t)o * DIN;
            float p0 = 0, p1 = 0, p2 = 0, p3 = 0;
            for (int jj = lane; jj < DIN; jj += 32) {
                float wv = xr[jj];
                p0 += S->xm[0][jj] * wv; p1 += S->xm[1][jj] * wv;
                p2 += S->xm[2][jj] * wv; p3 += S->xm[3][jj] * wv;
            }
#pragma unroll
            for (int off = 16; off; off >>= 1) {
                p0 += __shfl_down_sync(0xffffffffu, p0, off);
                p1 += __shfl_down_sync(0xffffffffu, p1, off);
                p2 += __shfl_down_sync(0xffffffffu, p2, off);
                p3 += __shfl_down_sync(0xffffffffu, p3, off);
            }
            if (lane == 0) {
                S->xdbl[0][o] = p0; S->xdbl[1][o] = p1;
                S->xdbl[2][o] = p2; S->xdbl[3][o] = p3;
            }
        }
        __syncthreads();
        if (tid < 4) {
            float s = 0.0f;
#pragma unroll
            for (int ss = 0; ss < DSTATE; ss++)
                s += S->xdbl[tid][DTRANK + ss] * S->xdbl[tid][DTRANK + DSTATE + ss];
            S->bcs[tid] = s;
        }
        __syncthreads();

        // D: delta = softplus(dt@dt_w^T + dt_b); y
#pragma unroll
        for (int oj = 0; oj < 2; oj++) {
            int j = tid + oj * 256;
            float wr[16];
#pragma unroll
            for (int q = 0; q < 4; q++)
                *(float4*)&wr[q * 4] = *(const float4*)(dt_w + (size_t)j * 16 + q * 4);
            float dtbj = S->dtb[j], dmj = S->dm[j];
#pragma unroll
            for (int r = 0; r < 4; r++) {
                float s = dtbj;
#pragma unroll
                for (int rr = 0; rr < 16; rr++) s += S->xdbl[r][rr] * wr[rr];
                float delta = fmaxf(s, 0.0f) + log1pf(__expf(-fabsf(s)));
                S->yv[r][j] = (delta * S->bcs[r] + dmj) * S->xm[r][j] * S->zs[r][j];
            }
        }
        __syncthreads();

        // E: mamba_out = y @ out_proj^T
        float acc1[1][4] = {{0, 0, 0, 0}};
        mv_accum<1>(S, out_proj, DIN, &S->yv[0][0], DIN, acc1, tid);

        // F: gates + state update
        int t_out = d ? (TLEN - 1 - t) : t;
#pragma unroll
        for (int r = 0; r < 4; r++) {
            float iv = sigmoidf_(acc1[0][r] + S->bsum[tid]);
            float fv = sigmoidf_(S->g[r][H + tid]     + S->bsum[H + tid]);
            float gv = tanhf(S->g[r][2 * H + tid]     + S->bsum[2 * H + tid]);
            float ov = sigmoidf_(S->g[r][3 * H + tid] + S->bsum[3 * H + tid]);
            float cn = fv * S->c[r][tid] + iv * gv;
            float hn = ov * tanhf(cn);
            S->c[r][tid] = cn;
            S->h[r][tid] = hn;
            outbuf[((size_t)(b0 + r) * TLEN + t_out) * 512 + d * H + tid] = hn;
        }
        __syncthreads();
    }

#pragma unroll
    for (int r = 0; r < 4; r++) {
        g_h[((size_t)d * BSZ + b0 + r) * H + tid] = S->h[r][tid];
        g_c[((size_t)d * BSZ + b0 + r) * H + tid] = S->c[r][tid];
    }
}

extern "C" void kernel_launch(void* const* d_in, const int* in_sizes, int n_in,
                              void* d_out, int out_size)
{
    (void)in_sizes; (void)n_in;
    const float* x        = (const float*)d_in[0];
    const float* w_ih_l0  = (const float*)d_in[1];
    const float* w_hh_l0  = (const float*)d_in[2];
    const float* b_ih_l0  = (const float*)d_in[3];
    const float* b_hh_l0  = (const float*)d_in[4];
    const float* w_ih_l1  = (const float*)d_in[5];
    const float* w_hh_l1  = (const float*)d_in[6];
    const float* b_ih_l1  = (const float*)d_in[7];
    const float* b_hh_l1  = (const float*)d_in[8];
    const float* in_proj  = (const float*)d_in[9];
    const float* conv_w   = (const float*)d_in[10];
    const float* conv_b   = (const float*)d_in[11];
    const float* x_proj   = (const float*)d_in[12];
    const float* dt_w     = (const float*)d_in[13];
    const float* dt_b     = (const float*)d_in[14];
    const float* Dm       = (const float*)d_in[15];
    const float* out_proj = (const float*)d_in[16];
    float* out = (float*)d_out;
    (void)out_size;

    static int smem_set = 0;
    int smem_bytes = (int)sizeof(ScanSmem);
    if (!smem_set) {
        cudaFuncSetAttribute(scan_kernel, cudaFuncAttributeMaxDynamicSharedMemorySize, smem_bytes);
        smem_set = 1;
    }

    float* out0;
    cudaGetSymbolAddress((void**)&out0, g_out0);

    dim3 grid_wx(8, 256, 2);
    // layer 0
    wx_gemm_kernel<<<grid_wx, 256>>>(x, w_ih_l0, 128);
    scan_kernel<<<128, 256, smem_bytes>>>(w_hh_l0, b_ih_l0, b_hh_l0,
        in_proj, conv_w, conv_b, x_proj, dt_w, dt_b, Dm, out_proj, out0, 1);
    // layer 1
    wx_gemm_kernel<<<grid_wx, 256>>>(out0, w_ih_l1, 512);
    scan_kernel<<<128, 256, smem_bytes>>>(w_hh_l1, b_ih_l1, b_hh_l1,
        in_proj, conv_w, conv_b, x_proj, dt_w, dt_b, Dm, out_proj, out, 0);
}

// round 3
// speedup vs baseline: 1.0127x; 1.0127x over previous
#include <cuda_runtime.h>
#include <cuda_fp16.h>
#include <math.h>
#include <stdint.h>

#define H       256
#define BSZ     256
#define TLEN    128
#define G4      1024
#define DIN     512

// ---------------- device scratch (no allocations) ----------------
__device__ float  g_wx[(size_t)2 * TLEN * BSZ * G4];
__device__ float  g_out0[(size_t)BSZ * TLEN * 512];
__device__ float  g_h[2 * BSZ * H];
__device__ float  g_c[2 * BSZ * H];
__device__ __half g_whh0t[2 * H * G4];   // [d][k=256][j=1024]
__device__ __half g_whh1t[2 * H * G4];
__device__ __half g_inpt[H * G4];        // [k=256][j=1024]
__device__ __half g_outpt[DIN * H];      // [k=512][j=256]
__device__ __half g_xph[48 * DIN];       // row-major copy

__device__ __forceinline__ float sigmoidf_(float x) { return 1.0f / (1.0f + __expf(-x)); }

__device__ __forceinline__ void ffma2(unsigned long long &d, unsigned long long a, unsigned long long b) {
    asm("fma.rn.f32x2 %0, %1, %2, %0;" : "+l"(d) : "l"(a), "l"(b));
}
__device__ __forceinline__ unsigned long long pack2(float x, float y) {
    unsigned long long r; asm("mov.b64 %0, {%1, %2};" : "=l"(r) : "f"(x), "f"(y)); return r;
}
__device__ __forceinline__ float2 unpack2(unsigned long long v) {
    float2 r; asm("mov.b64 {%0, %1}, %2;" : "=f"(r.x), "=f"(r.y) : "l"(v)); return r;
}

// ---------------- weight prep kernels (run every launch; tiny) ----------------
__global__ void transpose_h_kernel(const float* __restrict__ W, __half* __restrict__ Wt,
                                   int J, int K)
{
    __shared__ float t[32][33];
    const float* Wb = W + (size_t)blockIdx.z * J * K;
    __half* Wtb = Wt + (size_t)blockIdx.z * J * K;
    int j0 = blockIdx.y * 32, k0 = blockIdx.x * 32;
    int tx = threadIdx.x, ty = threadIdx.y;
    t[ty][tx] = Wb[(size_t)(j0 + ty) * K + k0 + tx];
    __syncthreads();
    Wtb[(size_t)(k0 + ty) * J + j0 + tx] = __float2half(t[tx][ty]);
}

__global__ void convert_h_kernel(const float* __restrict__ src, __half* __restrict__ dst, int n)
{
    int i = blockIdx.x * blockDim.x + threadIdx.x;
    if (i < n) dst[i] = __float2half(src[i]);
}

// ---------------- wx GEMM (unchanged from passing version) ----------------
__global__ void wx_gemm_kernel(const float* __restrict__ Ain,
                               const float* __restrict__ W, int K)
{
    const int d  = blockIdx.z;
    const int n0 = blockIdx.x * 128;
    const int m0 = blockIdx.y * 128;
    const int tid = threadIdx.x;
    const int tx = tid & 15, ty = tid >> 4;

    __shared__ float As[16][132];
    __shared__ float Bs[16][132];

    const float* Wd = W + (size_t)d * G4 * K;
    float acc[8][8];
#pragma unroll
    for (int i = 0; i < 8; i++)
#pragma unroll
        for (int j = 0; j < 8; j++) acc[i][j] = 0.0f;

    const int lr = tid >> 1;
    const int lk = (tid & 1) * 4;
    const int mA = m0 + lr;
    const int tA = mA >> 8;
    const int bA = mA & 255;
    const int tsA = d ? (TLEN - 1 - tA) : tA;
    const float* arow = Ain + ((size_t)bA * TLEN + tsA) * K;
    const float* brow = Wd + (size_t)(n0 + lr) * K;

    for (int k0 = 0; k0 < K; k0 += 16) {
#pragma unroll
        for (int l = 0; l < 2; l++) {
            int kk = lk + l * 8;
            float4 a4 = *(const float4*)(arow + k0 + kk);
            As[kk + 0][lr] = a4.x; As[kk + 1][lr] = a4.y;
            As[kk + 2][lr] = a4.z; As[kk + 3][lr] = a4.w;
            float4 b4 = *(const float4*)(brow + k0 + kk);
            Bs[kk + 0][lr] = b4.x; Bs[kk + 1][lr] = b4.y;
            Bs[kk + 2][lr] = b4.z; Bs[kk + 3][lr] = b4.w;
        }
        __syncthreads();
#pragma unroll
        for (int kk = 0; kk < 16; kk++) {
            float av[8], bv[8];
            *(float4*)&av[0] = *(const float4*)&As[kk][ty * 8];
            *(float4*)&av[4] = *(const float4*)&As[kk][ty * 8 + 4];
            *(float4*)&bv[0] = *(const float4*)&Bs[kk][tx * 8];
            *(float4*)&bv[4] = *(const float4*)&Bs[kk][tx * 8 + 4];
#pragma unroll
            for (int i = 0; i < 8; i++)
#pragma unroll
                for (int j = 0; j < 8; j++) acc[i][j] += av[i] * bv[j];
        }
        __syncthreads();
    }
#pragma unroll
    for (int i = 0; i < 8; i++) {
        int m = m0 + ty * 8 + i;
        int t = m >> 8;
        int b = m & 255;
        float* orow = g_wx + (((size_t)d * TLEN + t) * BSZ + b) * G4 + n0 + tx * 8;
        *(float4*)(orow)     = make_float4(acc[i][0], acc[i][1], acc[i][2], acc[i][3]);
        *(float4*)(orow + 4) = make_float4(acc[i][4], acc[i][5], acc[i][6], acc[i][7]);
    }
}

// ---------------- scan SMEM ----------------
struct SS {
    __half sw[2][16 * 1024];   // weight tile double buffer (A/B: 16kk x 1024j; E: 32kk x 256j)
    float4 h4[H];              // h transposed: [k][r]
    float4 u4[H];              // g[:, :H] transposed
    float4 yv4[DIN];           // y transposed
    float4 gt4[3][H];          // f,g,o gate pre-activations, [gate][j][r]
    float  c[4][H];
    float  xm[4][DIN];
    float  zs[4][DIN];
    float  xdbl[4][48];
    float  bsum[G4];
    float  cw1[DIN], cb[DIN], dm[DIN], dtb[DIN];
    float  dtw[DIN * 16];
    __half xp[48 * DIN];
    float  bcs[4];
};

// Phase A/B matvec: J=1024, thread owns j4 = tid*4 .. +3; acc2[jj] = {(r0,r1),(r2,r3)}
template<int KDIM>
__device__ __forceinline__ void mv_big(SS* S, const __half* __restrict__ Wt,
                                       const float4* __restrict__ act4,
                                       unsigned long long (&acc2)[4][2], int tid)
{
    const int NT = KDIM / 16;
    uint4 stg[8];
    {
        const uint4* gs = (const uint4*)Wt;
#pragma unroll
        for (int c = 0; c < 8; c++) stg[c] = gs[tid + c * 256];
        uint4* sd = (uint4*)S->sw[0];
#pragma unroll
        for (int c = 0; c < 8; c++) sd[tid + c * 256] = stg[c];
    }
    __syncthreads();
    const int j4 = tid * 4;
    for (int ti = 0; ti < NT; ti++) {
        if (ti + 1 < NT) {
            const uint4* gs = (const uint4*)(Wt + (size_t)(ti + 1) * 16 * 1024);
#pragma unroll
            for (int c = 0; c < 8; c++) stg[c] = gs[tid + c * 256];
        }
        const __half* wb = S->sw[ti & 1];
        const float4* ab = act4 + ti * 16;
#pragma unroll
        for (int kk = 0; kk < 16; kk++) {
            uint2 w4 = *(const uint2*)(wb + kk * 1024 + j4);
            float2 w01 = __half22float2(*(const __half2*)&w4.x);
            float2 w23 = __half22float2(*(const __half2*)&w4.y);
            ulonglong2 av = *(const ulonglong2*)(ab + kk);
            unsigned long long p;
            p = pack2(w01.x, w01.x); ffma2(acc2[0][0], p, av.x); ffma2(acc2[0][1], p, av.y);
            p = pack2(w01.y, w01.y); ffma2(acc2[1][0], p, av.x); ffma2(acc2[1][1], p, av.y);
            p = pack2(w23.x, w23.x); ffma2(acc2[2][0], p, av.x); ffma2(acc2[2][1], p, av.y);
            p = pack2(w23.y, w23.y); ffma2(acc2[3][0], p, av.x); ffma2(acc2[3][1], p, av.y);
        }
        if (ti + 1 < NT) {
            uint4* sd = (uint4*)S->sw[(ti + 1) & 1];
#pragma unroll
            for (int c = 0; c < 8; c++) sd[tid + c * 256] = stg[c];
        }
        __syncthreads();
    }
}

// Phase E matvec: J=256 (j = tid), K=512, tiles of 32 kk x 256 j
__device__ __forceinline__ void mv_small(SS* S, const __half* __restrict__ Wt,
                                         const float4* __restrict__ act4,
                                         unsigned long long (&acc2)[2], int tid)
{
    const int NT = 512 / 32;
    uint4 stg[4];
    {
        const uint4* gs = (const uint4*)Wt;
#pragma unroll
        for (int c = 0; c < 4; c++) stg[c] = gs[tid + c * 256];
        uint4* sd = (uint4*)S->sw[0];
#pragma unroll
        for (int c = 0; c < 4; c++) sd[tid + c * 256] = stg[c];
    }
    __syncthreads();
    for (int ti = 0; ti < NT; ti++) {
        if (ti + 1 < NT) {
            const uint4* gs = (const uint4*)(Wt + (size_t)(ti + 1) * 32 * 256);
#pragma unroll
            for (int c = 0; c < 4; c++) stg[c] = gs[tid + c * 256];
        }
        const __half* wb = S->sw[ti & 1];
        const float4* ab = act4 + ti * 32;
#pragma unroll
        for (int kk = 0; kk < 32; kk++) {
            float w = __half2float(wb[kk * 256 + tid]);
            ulonglong2 av = *(const ulonglong2*)(ab + kk);
            unsigned long long p = pack2(w, w);
            ffma2(acc2[0], p, av.x);
            ffma2(acc2[1], p, av.y);
        }
        if (ti + 1 < NT) {
            uint4* sd = (uint4*)S->sw[(ti + 1) & 1];
#pragma unroll
            for (int c = 0; c < 4; c++) sd[tid + c * 256] = stg[c];
        }
        __syncthreads();
    }
}

__global__ __launch_bounds__(256) void scan_kernel(
    const __half* __restrict__ whh_t,     // [2][256][1024]
    const float*  __restrict__ bih,
    const float*  __restrict__ bhh,
    const __half* __restrict__ inp_t,     // [256][1024]
    const __half* __restrict__ outp_t,    // [512][256]
    const __half* __restrict__ xp_h,      // [48][512]
    const float*  __restrict__ conv_w,
    const float*  __restrict__ conv_b,
    const float*  __restrict__ dt_w,
    const float*  __restrict__ dt_b,
    const float*  __restrict__ Dm,
    float* __restrict__ outbuf,
    int first_layer)
{
    extern __shared__ char sraw[];
    SS* S = (SS*)sraw;
    const int tid = threadIdx.x;
    const int d   = blockIdx.x >> 6;
    const int b0  = (blockIdx.x & 63) * 4;
    const int wid = tid >> 5, lane = tid & 31;
    const __half* whh_d = whh_t + (size_t)d * H * G4;

    // ---- persistent SMEM init ----
#pragma unroll
    for (int i = 0; i < 4; i++) {
        int j = tid + i * 256;
        S->bsum[j] = bih[d * G4 + j] + bhh[d * G4 + j];
    }
#pragma unroll
    for (int i = 0; i < 2; i++) {
        int j = tid + i * 256;
        S->cw1[j] = conv_w[j * 2 + 1];
        S->cb[j]  = conv_b[j];
        S->dm[j]  = Dm[j];
        S->dtb[j] = dt_b[j];
    }
    for (int i = tid; i < DIN * 16 / 4; i += 256)
        ((float4*)S->dtw)[i] = ((const float4*)dt_w)[i];
    for (int i = tid; i < 48 * DIN / 8; i += 256)
        ((uint4*)S->xp)[i] = ((const uint4*)xp_h)[i];
    if (first_layer) {
        S->h4[tid] = make_float4(0.f, 0.f, 0.f, 0.f);
#pragma unroll
        for (int r = 0; r < 4; r++) S->c[r][tid] = 0.0f;
    } else {
        float hv[4];
#pragma unroll
        for (int r = 0; r < 4; r++) {
            hv[r] = g_h[((size_t)d * BSZ + b0 + r) * H + tid];
            S->c[r][tid] = g_c[((size_t)d * BSZ + b0 + r) * H + tid];
        }
        S->h4[tid] = make_float4(hv[0], hv[1], hv[2], hv[3]);
    }
    __syncthreads();

    const float* wxbase = g_wx + ((size_t)d * TLEN) * BSZ * G4 + (size_t)b0 * G4;
    const int j4 = tid * 4;

    for (int t = 0; t < TLEN; t++) {
        // ---------- Phase A: g = wx_t + h @ Whh^T ----------
        unsigned long long acc2[4][2];
        {
            const float* wxr = wxbase + (size_t)t * BSZ * G4;
            float r0[4], r1[4], r2[4], r3[4];
            *(float4*)r0 = *(const float4*)(wxr + 0 * G4 + j4);
            *(float4*)r1 = *(const float4*)(wxr + 1 * G4 + j4);
            *(float4*)r2 = *(const float4*)(wxr + 2 * G4 + j4);
            *(float4*)r3 = *(const float4*)(wxr + 3 * G4 + j4);
#pragma unroll
            for (int jj = 0; jj < 4; jj++) {
                acc2[jj][0] = pack2(r0[jj], r1[jj]);
                acc2[jj][1] = pack2(r2[jj], r3[jj]);
            }
        }
        mv_big<H>(S, whh_d, S->h4, acc2, tid);
        if (tid < 64) {
#pragma unroll
            for (int jj = 0; jj < 4; jj++) {
                float2 a = unpack2(acc2[jj][0]);
                float2 b = unpack2(acc2[jj][1]);
                S->u4[j4 + jj] = make_float4(a.x, a.y, b.x, b.y);
            }
        } else {
            int gi = (j4 >> 8) - 1;
            int jo = j4 & 255;
#pragma unroll
            for (int jj = 0; jj < 4; jj++) {
                float2 a = unpack2(acc2[jj][0]);
                float2 b = unpack2(acc2[jj][1]);
                S->gt4[gi][jo + jj] = make_float4(a.x, a.y, b.x, b.y);
            }
        }

        // ---------- Phase B: xz = u @ in_proj^T ----------
#pragma unroll
        for (int jj = 0; jj < 4; jj++) { acc2[jj][0] = 0ull; acc2[jj][1] = 0ull; }
        mv_big<H>(S, inp_t, S->u4, acc2, tid);
        {
            float v[4][4];   // [jj][r]
#pragma unroll
            for (int jj = 0; jj < 4; jj++) {
                float2 a = unpack2(acc2[jj][0]);
                float2 b = unpack2(acc2[jj][1]);
                v[jj][0] = a.x; v[jj][1] = a.y; v[jj][2] = b.x; v[jj][3] = b.y;
            }
            if (tid < 128) {
                float cw[4], cbv[4];
                *(float4*)cw  = *(const float4*)&S->cw1[j4];
                *(float4*)cbv = *(const float4*)&S->cb[j4];
#pragma unroll
                for (int r = 0; r < 4; r++) {
                    float o[4];
#pragma unroll
                    for (int jj = 0; jj < 4; jj++) {
                        float pre = v[jj][r] * cw[jj] + cbv[jj];
                        o[jj] = pre * sigmoidf_(pre);
                    }
                    *(float4*)&S->xm[r][j4] = *(float4*)o;
                }
            } else {
                int jz = j4 - 512;
#pragma unroll
                for (int r = 0; r < 4; r++) {
                    float o[4];
#pragma unroll
                    for (int jj = 0; jj < 4; jj++) {
                        float z = v[jj][r];
                        o[jj] = z * sigmoidf_(z);
                    }
                    *(float4*)&S->zs[r][jz] = *(float4*)o;
                }
            }
        }
        __syncthreads();

        // ---------- Phase C: x_dbl = xm @ x_proj^T ----------
        for (int o = wid; o < 48; o += 8) {
            const __half* xr = S->xp + o * DIN;
            float p0 = 0, p1 = 0, p2 = 0, p3 = 0;
            for (int jj = lane; jj < DIN; jj += 32) {
                float wv = __half2float(xr[jj]);
                p0 += S->xm[0][jj] * wv; p1 += S->xm[1][jj] * wv;
                p2 += S->xm[2][jj] * wv; p3 += S->xm[3][jj] * wv;
            }
#pragma unroll
            for (int off = 16; off; off >>= 1) {
                p0 += __shfl_down_sync(0xffffffffu, p0, off);
                p1 += __shfl_down_sync(0xffffffffu, p1, off);
                p2 += __shfl_down_sync(0xffffffffu, p2, off);
                p3 += __shfl_down_sync(0xffffffffu, p3, off);
            }
            if (lane == 0) {
                S->xdbl[0][o] = p0; S->xdbl[1][o] = p1;
                S->xdbl[2][o] = p2; S->xdbl[3][o] = p3;
            }
        }
        __syncthreads();
        if (tid < 4) {
            float s = 0.0f;
#pragma unroll
            for (int ss = 0; ss < 16; ss++)
                s += S->xdbl[tid][16 + ss] * S->xdbl[tid][32 + ss];
            S->bcs[tid] = s;
        }
        __syncthreads();

        // ---------- Phase D: delta/softplus, y ----------
#pragma unroll
        for (int oj = 0; oj < 2; oj++) {
            int j = tid + oj * 256;
            float wr[16];
#pragma unroll
            for (int q = 0; q < 4; q++)
                *(float4*)&wr[q * 4] = *(const float4*)&S->dtw[j * 16 + q * 4];
            float dtbj = S->dtb[j], dmj = S->dm[j];
            float yv[4];
#pragma unroll
            for (int r = 0; r < 4; r++) {
                float s = dtbj;
#pragma unroll
                for (int rr = 0; rr < 16; rr++) s += S->xdbl[r][rr] * wr[rr];
                float delta = fmaxf(s, 0.0f) + log1pf(__expf(-fabsf(s)));
                yv[r] = (delta * S->bcs[r] + dmj) * S->xm[r][j] * S->zs[r][j];
            }
            S->yv4[j] = make_float4(yv[0], yv[1], yv[2], yv[3]);
        }

        // ---------- Phase E: mamba_out = y @ out_proj^T ----------
        unsigned long long e2[2] = {0ull, 0ull};
        mv_small(S, outp_t, S->yv4, e2, tid);
        float2 m01 = unpack2(e2[0]);
        float2 m23 = unpack2(e2[1]);
        float mo[4] = {m01.x, m01.y, m23.x, m23.y};

        // ---------- Phase F: gates, state update, output ----------
        {
            int t_out = d ? (TLEN - 1 - t) : t;
            float bs_i = S->bsum[tid];
            float bs_f = S->bsum[H + tid];
            float bs_g = S->bsum[2 * H + tid];
            float bs_o = S->bsum[3 * H + tid];
            float4 gf = S->gt4[0][tid];
            float4 gg = S->gt4[1][tid];
            float4 go = S->gt4[2][tid];
            float fa[4] = {gf.x, gf.y, gf.z, gf.w};
            float ga[4] = {gg.x, gg.y, gg.z, gg.w};
            float oa[4] = {go.x, go.y, go.z, go.w};
            float hv[4];
#pragma unroll
            for (int r = 0; r < 4; r++) {
                float iv = sigmoidf_(mo[r] + bs_i);
                float fv = sigmoidf_(fa[r] + bs_f);
                float gv = tanhf(ga[r] + bs_g);
                float ov = sigmoidf_(oa[r] + bs_o);
                float cn = fv * S->c[r][tid] + iv * gv;
                float hn = ov * tanhf(cn);
                S->c[r][tid] = cn;
                hv[r] = hn;
                outbuf[((size_t)(b0 + r) * TLEN + t_out) * 512 + d * H + tid] = hn;
            }
            S->h4[tid] = make_float4(hv[0], hv[1], hv[2], hv[3]);
        }
        // next iteration's mv_big prologue barrier orders h4 write vs reads
    }

    {
        float4 hf = S->h4[tid];
        float hv[4] = {hf.x, hf.y, hf.z, hf.w};
#pragma unroll
        for (int r = 0; r < 4; r++) {
            g_h[((size_t)d * BSZ + b0 + r) * H + tid] = hv[r];
            g_c[((size_t)d * BSZ + b0 + r) * H + tid] = S->c[r][tid];
        }
    }
}

// =====================================================================
extern "C" void kernel_launch(void* const* d_in, const int* in_sizes, int n_in,
                              void* d_out, int out_size)
{
    (void)in_sizes; (void)n_in; (void)out_size;
    const float* x        = (const float*)d_in[0];
    const float* w_ih_l0  = (const float*)d_in[1];
    const float* w_hh_l0  = (const float*)d_in[2];
    const float* b_ih_l0  = (const float*)d_in[3];
    const float* b_hh_l0  = (const float*)d_in[4];
    const float* w_ih_l1  = (const float*)d_in[5];
    const float* w_hh_l1  = (const float*)d_in[6];
    const float* b_ih_l1  = (const float*)d_in[7];
    const float* b_hh_l1  = (const float*)d_in[8];
    const float* in_proj  = (const float*)d_in[9];
    const float* conv_w   = (const float*)d_in[10];
    const float* conv_b   = (const float*)d_in[11];
    const float* x_proj   = (const float*)d_in[12];
    const float* dt_w     = (const float*)d_in[13];
    const float* dt_b     = (const float*)d_in[14];
    const float* Dm       = (const float*)d_in[15];
    const float* out_proj = (const float*)d_in[16];
    float* out = (float*)d_out;

    static int inited = 0;
    int smem_bytes = (int)sizeof(SS);
    if (!inited) {
        cudaFuncSetAttribute(scan_kernel, cudaFuncAttributeMaxDynamicSharedMemorySize, smem_bytes);
        inited = 1;
    }

    float* out0;   cudaGetSymbolAddress((void**)&out0, g_out0);
    __half* whh0t; cudaGetSymbolAddress((void**)&whh0t, g_whh0t);
    __half* whh1t; cudaGetSymbolAddress((void**)&whh1t, g_whh1t);
    __half* inpt;  cudaGetSymbolAddress((void**)&inpt,  g_inpt);
    __half* outpt; cudaGetSymbolAddress((void**)&outpt, g_outpt);
    __half* xph;   cudaGetSymbolAddress((void**)&xph,   g_xph);

    dim3 tb(32, 32);
    transpose_h_kernel<<<dim3(256 / 32, 1024 / 32, 2), tb>>>(w_hh_l0, whh0t, G4, H);
    transpose_h_kernel<<<dim3(256 / 32, 1024 / 32, 2), tb>>>(w_hh_l1, whh1t, G4, H);
    transpose_h_kernel<<<dim3(256 / 32, 1024 / 32, 1), tb>>>(in_proj, inpt, G4, H);
    transpose_h_kernel<<<dim3(512 / 32, 256 / 32, 1), tb>>>(out_proj, outpt, H, DIN);
    convert_h_kernel<<<(48 * DIN + 255) / 256, 256>>>(x_proj, xph, 48 * DIN);

    dim3 grid_wx(8, 256, 2);
    // layer 0
    wx_gemm_kernel<<<grid_wx, 256>>>(x, w_ih_l0, 128);
    scan_kernel<<<128, 256, smem_bytes>>>(whh0t, b_ih_l0, b_hh_l0,
        inpt, outpt, xph, conv_w, conv_b, dt_w, dt_b, Dm, out0, 1);
    // layer 1
    wx_gemm_kernel<<<grid_wx, 256>>>(out0, w_ih_l1, 512);
    scan_kernel<<<128, 256, smem_bytes>>>(whh1t, b_ih_l1, b_hh_l1,
        inpt, outpt, xph, conv_w, conv_b, dt_w, dt_b, Dm, out, 0);
}

// round 5
// speedup vs baseline: 1.6495x; 1.6287x over previous
#include <cuda_runtime.h>
#include <cuda_fp16.h>
#include <math.h>
#include <stdint.h>

#define H       256
#define BSZ     256
#define TLEN    128
#define G4      1024
#define DIN     512

// ---------------- device scratch (no allocations) ----------------
__device__ float  g_wx[(size_t)2 * TLEN * BSZ * G4];
__device__ float  g_out0[(size_t)BSZ * TLEN * 512];
__device__ float  g_h[2 * BSZ * H];
__device__ float  g_c[2 * BSZ * H];
__device__ __half g_whh0t[2 * H * G4];   // [d][k=256][j=1024]
__device__ __half g_whh1t[2 * H * G4];
__device__ __half g_inpt[H * G4];        // [k=256][j=1024]
__device__ __half g_outpt[DIN * H];      // [k=512][j=256]
__device__ __half g_xph[48 * DIN];       // row-major copy

__device__ __forceinline__ float sigmoidf_(float x) { return 1.0f / (1.0f + __expf(-x)); }

__device__ __forceinline__ void ffma2(unsigned long long &d, unsigned long long a, unsigned long long b) {
    asm("fma.rn.f32x2 %0, %1, %2, %0;" : "+l"(d) : "l"(a), "l"(b));
}
__device__ __forceinline__ unsigned long long pack2(float x, float y) {
    unsigned long long r; asm("mov.b64 %0, {%1, %2};" : "=l"(r) : "f"(x), "f"(y)); return r;
}
__device__ __forceinline__ float2 unpack2(unsigned long long v) {
    float2 r; asm("mov.b64 {%0, %1}, %2;" : "=f"(r.x), "=f"(r.y) : "l"(v)); return r;
}

// ---------------- weight prep kernels (run every launch; tiny) ----------------
__global__ void transpose_h_kernel(const float* __restrict__ W, __half* __restrict__ Wt,
                                   int J, int K)
{
    __shared__ float t[32][33];
    const float* Wb = W + (size_t)blockIdx.z * J * K;
    __half* Wtb = Wt + (size_t)blockIdx.z * J * K;
    int j0 = blockIdx.y * 32, k0 = blockIdx.x * 32;
    int tx = threadIdx.x, ty = threadIdx.y;
    t[ty][tx] = Wb[(size_t)(j0 + ty) * K + k0 + tx];
    __syncthreads();
    Wtb[(size_t)(k0 + ty) * J + j0 + tx] = __float2half(t[tx][ty]);
}

__global__ void convert_h_kernel(const float* __restrict__ src, __half* __restrict__ dst, int n)
{
    int i = blockIdx.x * blockDim.x + threadIdx.x;
    if (i < n) dst[i] = __float2half(src[i]);
}

// ---------------- wx GEMM (unchanged from passing version) ----------------
__global__ void wx_gemm_kernel(const float* __restrict__ Ain,
                               const float* __restrict__ W, int K)
{
    const int d  = blockIdx.z;
    const int n0 = blockIdx.x * 128;
    const int m0 = blockIdx.y * 128;
    const int tid = threadIdx.x;
    const int tx = tid & 15, ty = tid >> 4;

    __shared__ float As[16][132];
    __shared__ float Bs[16][132];

    const float* Wd = W + (size_t)d * G4 * K;
    float acc[8][8];
#pragma unroll
    for (int i = 0; i < 8; i++)
#pragma unroll
        for (int j = 0; j < 8; j++) acc[i][j] = 0.0f;

    const int lr = tid >> 1;
    const int lk = (tid & 1) * 4;
    const int mA = m0 + lr;
    const int tA = mA >> 8;
    const int bA = mA & 255;
    const int tsA = d ? (TLEN - 1 - tA) : tA;
    const float* arow = Ain + ((size_t)bA * TLEN + tsA) * K;
    const float* brow = Wd + (size_t)(n0 + lr) * K;

    for (int k0 = 0; k0 < K; k0 += 16) {
#pragma unroll
        for (int l = 0; l < 2; l++) {
            int kk = lk + l * 8;
            float4 a4 = *(const float4*)(arow + k0 + kk);
            As[kk + 0][lr] = a4.x; As[kk + 1][lr] = a4.y;
            As[kk + 2][lr] = a4.z; As[kk + 3][lr] = a4.w;
            float4 b4 = *(const float4*)(brow + k0 + kk);
            Bs[kk + 0][lr] = b4.x; Bs[kk + 1][lr] = b4.y;
            Bs[kk + 2][lr] = b4.z; Bs[kk + 3][lr] = b4.w;
        }
        __syncthreads();
#pragma unroll
        for (int kk = 0; kk < 16; kk++) {
            float av[8], bv[8];
            *(float4*)&av[0] = *(const float4*)&As[kk][ty * 8];
            *(float4*)&av[4] = *(const float4*)&As[kk][ty * 8 + 4];
            *(float4*)&bv[0] = *(const float4*)&Bs[kk][tx * 8];
            *(float4*)&bv[4] = *(const float4*)&Bs[kk][tx * 8 + 4];
#pragma unroll
            for (int i = 0; i < 8; i++)
#pragma unroll
                for (int j = 0; j < 8; j++) acc[i][j] += av[i] * bv[j];
        }
        __syncthreads();
    }
#pragma unroll
    for (int i = 0; i < 8; i++) {
        int m = m0 + ty * 8 + i;
        int t = m >> 8;
        int b = m & 255;
        float* orow = g_wx + (((size_t)d * TLEN + t) * BSZ + b) * G4 + n0 + tx * 8;
        *(float4*)(orow)     = make_float4(acc[i][0], acc[i][1], acc[i][2], acc[i][3]);
        *(float4*)(orow + 4) = make_float4(acc[i][4], acc[i][5], acc[i][6], acc[i][7]);
    }
}

// ---------------- scan SMEM ----------------
struct SS {
    __half sw[2][16 * 1024];   // weight tile double buffer (A/B: 16kk x 1024j; E: 32kk x 256j)
    float4 h4[H];              // h transposed: [k][r]
    float4 u4[H];              // g[:, :H] transposed
    float4 yv4[DIN];           // y transposed
    float4 gt4[3][H];          // f,g,o gate pre-activations, [gate][j][r]
    float  c[4][H];
    float  xm[4][DIN];
    float  zs[4][DIN];
    float  xdbl[4][48];
    float  bsum[G4];
    float  cw1[DIN], cb[DIN], dm[DIN], dtb[DIN];
    float  dtw[DIN * 16];
    __half xp[48 * DIN];
    float  bcs[4];
};

// Phase A/B matvec: J=1024, thread owns j4 = tid*4 .. +3; acc2[jj] = {(r0,r1),(r2,r3)}
template<int KDIM>
__device__ __forceinline__ void mv_big(SS* S, const __half* __restrict__ Wt,
                                       const float4* __restrict__ act4,
                                       unsigned long long (&acc2)[4][2], int tid)
{
    const int NT = KDIM / 16;
    uint4 stg[8];
    {
        const uint4* gs = (const uint4*)Wt;
#pragma unroll
        for (int c = 0; c < 8; c++) stg[c] = gs[tid + c * 256];
        uint4* sd = (uint4*)S->sw[0];
#pragma unroll
        for (int c = 0; c < 8; c++) sd[tid + c * 256] = stg[c];
    }
    __syncthreads();
    const int j4 = tid * 4;
    for (int ti = 0; ti < NT; ti++) {
        if (ti + 1 < NT) {
            const uint4* gs = (const uint4*)(Wt + (size_t)(ti + 1) * 16 * 1024);
#pragma unroll
            for (int c = 0; c < 8; c++) stg[c] = gs[tid + c * 256];
        }
        const __half* wb = S->sw[ti & 1];
        const float4* ab = act4 + ti * 16;
#pragma unroll
        for (int kk = 0; kk < 16; kk++) {
            uint2 w4 = *(const uint2*)(wb + kk * 1024 + j4);
            float2 w01 = __half22float2(*(const __half2*)&w4.x);
            float2 w23 = __half22float2(*(const __half2*)&w4.y);
            ulonglong2 av = *(const ulonglong2*)(ab + kk);
            unsigned long long p;
            p = pack2(w01.x, w01.x); ffma2(acc2[0][0], p, av.x); ffma2(acc2[0][1], p, av.y);
            p = pack2(w01.y, w01.y); ffma2(acc2[1][0], p, av.x); ffma2(acc2[1][1], p, av.y);
            p = pack2(w23.x, w23.x); ffma2(acc2[2][0], p, av.x); ffma2(acc2[2][1], p, av.y);
            p = pack2(w23.y, w23.y); ffma2(acc2[3][0], p, av.x); ffma2(acc2[3][1], p, av.y);
        }
        if (ti + 1 < NT) {
            uint4* sd = (uint4*)S->sw[(ti + 1) & 1];
#pragma unroll
            for (int c = 0; c < 8; c++) sd[tid + c * 256] = stg[c];
        }
        __syncthreads();
    }
}

// Phase E matvec: J=256 (j = tid), K=512, tiles of 32 kk x 256 j
__device__ __forceinline__ void mv_small(SS* S, const __half* __restrict__ Wt,
                                         const float4* __restrict__ act4,
                                         unsigned long long (&acc2)[2], int tid)
{
    const int NT = 512 / 32;
    uint4 stg[4];
    {
        const uint4* gs = (const uint4*)Wt;
#pragma unroll
        for (int c = 0; c < 4; c++) stg[c] = gs[tid + c * 256];
        uint4* sd = (uint4*)S->sw[0];
#pragma unroll
        for (int c = 0; c < 4; c++) sd[tid + c * 256] = stg[c];
    }
    __syncthreads();
    for (int ti = 0; ti < NT; ti++) {
        if (ti + 1 < NT) {
            const uint4* gs = (const uint4*)(Wt + (size_t)(ti + 1) * 32 * 256);
#pragma unroll
            for (int c = 0; c < 4; c++) stg[c] = gs[tid + c * 256];
        }
        const __half* wb = S->sw[ti & 1];
        const float4* ab = act4 + ti * 32;
#pragma unroll
        for (int kk = 0; kk < 32; kk++) {
            float w = __half2float(wb[kk * 256 + tid]);
            ulonglong2 av = *(const ulonglong2*)(ab + kk);
            unsigned long long p = pack2(w, w);
            ffma2(acc2[0], p, av.x);
            ffma2(acc2[1], p, av.y);
        }
        if (ti + 1 < NT) {
            uint4* sd = (uint4*)S->sw[(ti + 1) & 1];
#pragma unroll
            for (int c = 0; c < 4; c++) sd[tid + c * 256] = stg[c];
        }
        __syncthreads();
    }
}

__global__ __launch_bounds__(256) void scan_kernel(
    const __half* __restrict__ whh_t,     // [2][256][1024]
    const float*  __restrict__ bih,
    const float*  __restrict__ bhh,
    const __half* __restrict__ inp_t,     // [256][1024]
    const __half* __restrict__ outp_t,    // [512][256]
    const __half* __restrict__ xp_h,      // [48][512]
    const float*  __restrict__ conv_w,
    const float*  __restrict__ conv_b,
    const float*  __restrict__ dt_w,
    const float*  __restrict__ dt_b,
    const float*  __restrict__ Dm,
    float* __restrict__ outbuf,
    int first_layer)
{
    extern __shared__ char sraw[];
    SS* S = (SS*)sraw;
    const int tid = threadIdx.x;
    const int d   = blockIdx.x >> 6;
    const int b0  = (blockIdx.x & 63) * 4;
    const int wid = tid >> 5, lane = tid & 31;
    const __half* whh_d = whh_t + (size_t)d * H * G4;

    // ---- persistent SMEM init ----
#pragma unroll
    for (int i = 0; i < 4; i++) {
        int j = tid + i * 256;
        S->bsum[j] = bih[d * G4 + j] + bhh[d * G4 + j];
    }
#pragma unroll
    for (int i = 0; i < 2; i++) {
        int j = tid + i * 256;
        S->cw1[j] = conv_w[j * 2 + 1];
        S->cb[j]  = conv_b[j];
        S->dm[j]  = Dm[j];
        S->dtb[j] = dt_b[j];
    }
    for (int i = tid; i < DIN * 16 / 4; i += 256)
        ((float4*)S->dtw)[i] = ((const float4*)dt_w)[i];
    for (int i = tid; i < 48 * DIN / 8; i += 256)
        ((uint4*)S->xp)[i] = ((const uint4*)xp_h)[i];
    if (first_layer) {
        S->h4[tid] = make_float4(0.f, 0.f, 0.f, 0.f);
#pragma unroll
        for (int r = 0; r < 4; r++) S->c[r][tid] = 0.0f;
    } else {
        float hv[4];
#pragma unroll
        for (int r = 0; r < 4; r++) {
            hv[r] = g_h[((size_t)d * BSZ + b0 + r) * H + tid];
            S->c[r][tid] = g_c[((size_t)d * BSZ + b0 + r) * H + tid];
        }
        S->h4[tid] = make_float4(hv[0], hv[1], hv[2], hv[3]);
    }
    __syncthreads();

    const float* wxbase = g_wx + ((size_t)d * TLEN) * BSZ * G4 + (size_t)b0 * G4;
    const int j4 = tid * 4;

    for (int t = 0; t < TLEN; t++) {
        // ---------- Phase A: g = wx_t + h @ Whh^T ----------
        unsigned long long acc2[4][2];
        {
            const float* wxr = wxbase + (size_t)t * BSZ * G4;
            float r0[4], r1[4], r2[4], r3[4];
            *(float4*)r0 = *(const float4*)(wxr + 0 * G4 + j4);
            *(float4*)r1 = *(const float4*)(wxr + 1 * G4 + j4);
            *(float4*)r2 = *(const float4*)(wxr + 2 * G4 + j4);
            *(float4*)r3 = *(const float4*)(wxr + 3 * G4 + j4);
#pragma unroll
            for (int jj = 0; jj < 4; jj++) {
                acc2[jj][0] = pack2(r0[jj], r1[jj]);
                acc2[jj][1] = pack2(r2[jj], r3[jj]);
            }
        }
        mv_big<H>(S, whh_d, S->h4, acc2, tid);
        if (tid < 64) {
#pragma unroll
            for (int jj = 0; jj < 4; jj++) {
                float2 a = unpack2(acc2[jj][0]);
                float2 b = unpack2(acc2[jj][1]);
                S->u4[j4 + jj] = make_float4(a.x, a.y, b.x, b.y);
            }
        } else {
            int gi = (j4 >> 8) - 1;
            int jo = j4 & 255;
#pragma unroll
            for (int jj = 0; jj < 4; jj++) {
                float2 a = unpack2(acc2[jj][0]);
                float2 b = unpack2(acc2[jj][1]);
                S->gt4[gi][jo + jj] = make_float4(a.x, a.y, b.x, b.y);
            }
        }

        // ---------- Phase B: xz = u @ in_proj^T ----------
#pragma unroll
        for (int jj = 0; jj < 4; jj++) { acc2[jj][0] = 0ull; acc2[jj][1] = 0ull; }
        mv_big<H>(S, inp_t, S->u4, acc2, tid);
        {
            float v[4][4];   // [jj][r]
#pragma unroll
            for (int jj = 0; jj < 4; jj++) {
                float2 a = unpack2(acc2[jj][0]);
                float2 b = unpack2(acc2[jj][1]);
                v[jj][0] = a.x; v[jj][1] = a.y; v[jj][2] = b.x; v[jj][3] = b.y;
            }
            if (tid < 128) {
                float cw[4], cbv[4];
                *(float4*)cw  = *(const float4*)&S->cw1[j4];
                *(float4*)cbv = *(const float4*)&S->cb[j4];
#pragma unroll
                for (int r = 0; r < 4; r++) {
                    float o[4];
#pragma unroll
                    for (int jj = 0; jj < 4; jj++) {
                        float pre = v[jj][r] * cw[jj] + cbv[jj];
                        o[jj] = pre * sigmoidf_(pre);
                    }
                    *(float4*)&S->xm[r][j4] = *(float4*)o;
                }
            } else {
                int jz = j4 - 512;
#pragma unroll
                for (int r = 0; r < 4; r++) {
                    float o[4];
#pragma unroll
                    for (int jj = 0; jj < 4; jj++) {
                        float z = v[jj][r];
                        o[jj] = z * sigmoidf_(z);
                    }
                    *(float4*)&S->zs[r][jz] = *(float4*)o;
                }
            }
        }
        __syncthreads();

        // ---------- Phase C: x_dbl = xm @ x_proj^T ----------
        for (int o = wid; o < 48; o += 8) {
            const __half* xr = S->xp + o * DIN;
            float p0 = 0, p1 = 0, p2 = 0, p3 = 0;
            for (int jj = lane; jj < DIN; jj += 32) {
                float wv = __half2float(xr[jj]);
                p0 += S->xm[0][jj] * wv; p1 += S->xm[1][jj] * wv;
                p2 += S->xm[2][jj] * wv; p3 += S->xm[3][jj] * wv;
            }
#pragma unroll
            for (int off = 16; off; off >>= 1) {
                p0 += __shfl_down_sync(0xffffffffu, p0, off);
                p1 += __shfl_down_sync(0xffffffffu, p1, off);
                p2 += __shfl_down_sync(0xffffffffu, p2, off);
                p3 += __shfl_down_sync(0xffffffffu, p3, off);
            }
            if (lane == 0) {
                S->xdbl[0][o] = p0; S->xdbl[1][o] = p1;
                S->xdbl[2][o] = p2; S->xdbl[3][o] = p3;
            }
        }
        __syncthreads();
        if (tid < 4) {
            float s = 0.0f;
#pragma unroll
            for (int ss = 0; ss < 16; ss++)
                s += S->xdbl[tid][16 + ss] * S->xdbl[tid][32 + ss];
            S->bcs[tid] = s;
        }
        __syncthreads();

        // ---------- Phase D: delta/softplus, y ----------
#pragma unroll
        for (int oj = 0; oj < 2; oj++) {
            int j = tid + oj * 256;
            float wr[16];
#pragma unroll
            for (int q = 0; q < 4; q++)
                *(float4*)&wr[q * 4] = *(const float4*)&S->dtw[j * 16 + q * 4];
            float dtbj = S->dtb[j], dmj = S->dm[j];
            float yv[4];
#pragma unroll
            for (int r = 0; r < 4; r++) {
                float s = dtbj;
#pragma unroll
                for (int rr = 0; rr < 16; rr++) s += S->xdbl[r][rr] * wr[rr];
                float delta = fmaxf(s, 0.0f) + log1pf(__expf(-fabsf(s)));
                yv[r] = (delta * S->bcs[r] + dmj) * S->xm[r][j] * S->zs[r][j];
            }
            S->yv4[j] = make_float4(yv[0], yv[1], yv[2], yv[3]);
        }

        // ---------- Phase E: mamba_out = y @ out_proj^T ----------
        unsigned long long e2[2] = {0ull, 0ull};
        mv_small(S, outp_t, S->yv4, e2, tid);
        float2 m01 = unpack2(e2[0]);
        float2 m23 = unpack2(e2[1]);
        float mo[4] = {m01.x, m01.y, m23.x, m23.y};

        // ---------- Phase F: gates, state update, output ----------
        {
            int t_out = d ? (TLEN - 1 - t) : t;
            float bs_i = S->bsum[tid];
            float bs_f = S->bsum[H + tid];
            float bs_g = S->bsum[2 * H + tid];
            float bs_o = S->bsum[3 * H + tid];
            float4 gf = S->gt4[0][tid];
            float4 gg = S->gt4[1][tid];
            float4 go = S->gt4[2][tid];
            float fa[4] = {gf.x, gf.y, gf.z, gf.w};
            float ga[4] = {gg.x, gg.y, gg.z, gg.w};
            float oa[4] = {go.x, go.y, go.z, go.w};
            float hv[4];
#pragma unroll
            for (int r = 0; r < 4; r++) {
                float iv = sigmoidf_(mo[r] + bs_i);
                float fv = sigmoidf_(fa[r] + bs_f);
                float gv = tanhf(ga[r] + bs_g);
                float ov = sigmoidf_(oa[r] + bs_o);
                float cn = fv * S->c[r][tid] + iv * gv;
                float hn = ov * tanhf(cn);
                S->c[r][tid] = cn;
                hv[r] = hn;
                outbuf[((size_t)(b0 + r) * TLEN + t_out) * 512 + d * H + tid] = hn;
            }
            S->h4[tid] = make_float4(hv[0], hv[1], hv[2], hv[3]);
        }
        // next iteration's mv_big prologue barrier orders h4 write vs reads
    }

    {
        float4 hf = S->h4[tid];
        float hv[4] = {hf.x, hf.y, hf.z, hf.w};
#pragma unroll
        for (int r = 0; r < 4; r++) {
            g_h[((size_t)d * BSZ + b0 + r) * H + tid] = hv[r];
            g_c[((size_t)d * BSZ + b0 + r) * H + tid] = S->c[r][tid];
        }
    }
}

// =====================================================================
extern "C" void kernel_launch(void* const* d_in, const int* in_sizes, int n_in,
                              void* d_out, int out_size)
{
    (void)in_sizes; (void)n_in; (void)out_size;
    const float* x        = (const float*)d_in[0];
    const float* w_ih_l0  = (const float*)d_in[1];
    const float* w_hh_l0  = (const float*)d_in[2];
    const float* b_ih_l0  = (const float*)d_in[3];
    const float* b_hh_l0  = (const float*)d_in[4];
    const float* w_ih_l1  = (const float*)d_in[5];
    const float* w_hh_l1  = (const float*)d_in[6];
    const float* b_ih_l1  = (const float*)d_in[7];
    const float* b_hh_l1  = (const float*)d_in[8];
    const float* in_proj  = (const float*)d_in[9];
    const float* conv_w   = (const float*)d_in[10];
    const float* conv_b   = (const float*)d_in[11];
    const float* x_proj   = (const float*)d_in[12];
    const float* dt_w     = (const float*)d_in[13];
    const float* dt_b     = (const float*)d_in[14];
    const float* Dm       = (const float*)d_in[15];
    const float* out_proj = (const float*)d_in[16];
    float* out = (float*)d_out;

    static int inited = 0;
    int smem_bytes = (int)sizeof(SS);
    if (!inited) {
        cudaFuncSetAttribute(scan_kernel, cudaFuncAttributeMaxDynamicSharedMemorySize, smem_bytes);
        inited = 1;
    }

    float* out0;   cudaGetSymbolAddress((void**)&out0, g_out0);
    __half* whh0t; cudaGetSymbolAddress((void**)&whh0t, g_whh0t);
    __half* whh1t; cudaGetSymbolAddress((void**)&whh1t, g_whh1t);
    __half* inpt;  cudaGetSymbolAddress((void**)&inpt,  g_inpt);
    __half* outpt; cudaGetSymbolAddress((void**)&outpt, g_outpt);
    __half* xph;   cudaGetSymbolAddress((void**)&xph,   g_xph);

    dim3 tb(32, 32);
    transpose_h_kernel<<<dim3(256 / 32, 1024 / 32, 2), tb>>>(w_hh_l0, whh0t, G4, H);
    transpose_h_kernel<<<dim3(256 / 32, 1024 / 32, 2), tb>>>(w_hh_l1, whh1t, G4, H);
    transpose_h_kernel<<<dim3(256 / 32, 1024 / 32, 1), tb>>>(in_proj, inpt, G4, H);
    transpose_h_kernel<<<dim3(512 / 32, 256 / 32, 1), tb>>>(out_proj, outpt, H, DIN);
    convert_h_kernel<<<(48 * DIN + 255) / 256, 256>>>(x_proj, xph, 48 * DIN);

    dim3 grid_wx(8, 256, 2);
    // layer 0
    wx_gemm_kernel<<<grid_wx, 256>>>(x, w_ih_l0, 128);
    scan_kernel<<<128, 256, smem_bytes>>>(whh0t, b_ih_l0, b_hh_l0,
        inpt, outpt, xph, conv_w, conv_b, dt_w, dt_b, Dm, out0, 1);
    // layer 1
    wx_gemm_kernel<<<grid_wx, 256>>>(out0, w_ih_l1, 512);
    scan_kernel<<<128, 256, smem_bytes>>>(whh1t, b_ih_l1, b_hh_l1,
        inpt, outpt, xph, conv_w, conv_b, dt_w, dt_b, Dm, out, 0);
}

// round 6
// speedup vs baseline: 2.8620x; 1.7351x over previous
#include <cuda_runtime.h>
#include <cuda_fp16.h>
#include <math.h>
#include <stdint.h>

#define H    256
#define BSZ  256
#define TLEN 128
#define G4   1024
#define DIN  512
#define SKA  264   // [n][k] act stride, K=256 (132 words %32==4 -> conflict-free)
#define SKB  520   // K=512 variant (260 words %32==4)

__device__ float  g_wx[(size_t)2 * TLEN * G4 * BSZ];   // [d][t][j][b]
__device__ float  g_out0[(size_t)BSZ * TLEN * 512];
__device__ float  g_h[2 * BSZ * H];
__device__ float  g_c[2 * BSZ * H];
__device__ __half g_whhf[2 * 16 * 64 * 256];   // frag layout [d][kt][mt][lane][8]
__device__ __half g_inpf[16 * 64 * 256];
__device__ __half g_outpf[32 * 16 * 256];
__device__ __half g_xpf[32 * 4 * 256];

__device__ __forceinline__ float sigf(float x) { return 1.0f / (1.0f + __expf(-x)); }

__device__ __forceinline__ void mma16816(float d[4], unsigned a0, unsigned a1, unsigned a2,
                                         unsigned a3, unsigned b0, unsigned b1) {
    asm volatile(
        "mma.sync.aligned.m16n8k16.row.col.f32.f16.f16.f32 "
        "{%0,%1,%2,%3},{%4,%5,%6,%7},{%8,%9},{%0,%1,%2,%3};"
        : "+f"(d[0]), "+f"(d[1]), "+f"(d[2]), "+f"(d[3])
        : "r"(a0), "r"(a1), "r"(a2), "r"(a3), "r"(b0), "r"(b1));
}

// W[j][k] row-major -> frag-native: out[((kt*MT+mt)*32+lane)*8 + h]
__global__ void prepfrag(const float* __restrict__ W, __half* __restrict__ out,
                         int MT, int KT, int J)
{
    int idx = blockIdx.x * 256 + threadIdx.x;
    if (idx >= MT * KT * 256) return;
    int h = idx & 7, lane = (idx >> 3) & 31;
    int tile = idx >> 8;
    int mt = tile % MT, kt = tile / MT;
    int reg = h >> 1;
    int j = mt * 16 + (lane >> 2) + (reg & 1) * 8;
    int k = kt * 16 + (lane & 3) * 2 + (reg >> 1) * 8 + (h & 1);
    out[idx] = (j < J) ? __float2half(W[(size_t)j * (KT * 16) + k]) : __float2half(0.0f);
}

// ---------------- wx GEMM -> g_wx[d][t][j][b] ----------------
__global__ void wx_gemm_kernel(const float* __restrict__ Ain,
                               const float* __restrict__ W, int K)
{
    const int dd = blockIdx.z;
    const int n0 = blockIdx.x * 128;
    const int m0 = blockIdx.y * 128;
    const int tid = threadIdx.x;
    const int tx = tid & 15, ty = tid >> 4;

    __shared__ float As[16][132];
    __shared__ float Bs[16][132];

    const float* Wd = W + (size_t)dd * G4 * K;
    float acc[8][8];
#pragma unroll
    for (int i = 0; i < 8; i++)
#pragma unroll
        for (int j = 0; j < 8; j++) acc[i][j] = 0.0f;

    const int lr = tid >> 1;
    const int lk = (tid & 1) * 4;
    const int mA = m0 + lr;
    const int tA = mA >> 8;
    const int bA = mA & 255;
    const int tsA = dd ? (TLEN - 1 - tA) : tA;
    const float* arow = Ain + ((size_t)bA * TLEN + tsA) * K;
    const float* brow = Wd + (size_t)(n0 + lr) * K;

    for (int k0 = 0; k0 < K; k0 += 16) {
#pragma unroll
        for (int l = 0; l < 2; l++) {
            int kk = lk + l * 8;
            float4 a4 = *(const float4*)(arow + k0 + kk);
            As[kk + 0][lr] = a4.x; As[kk + 1][lr] = a4.y;
            As[kk + 2][lr] = a4.z; As[kk + 3][lr] = a4.w;
            float4 b4 = *(const float4*)(brow + k0 + kk);
            Bs[kk + 0][lr] = b4.x; Bs[kk + 1][lr] = b4.y;
            Bs[kk + 2][lr] = b4.z; Bs[kk + 3][lr] = b4.w;
        }
        __syncthreads();
#pragma unroll
        for (int kk = 0; kk < 16; kk++) {
            float av[8], bv[8];
            *(float4*)&av[0] = *(const float4*)&As[kk][ty * 8];
            *(float4*)&av[4] = *(const float4*)&As[kk][ty * 8 + 4];
            *(float4*)&bv[0] = *(const float4*)&Bs[kk][tx * 8];
            *(float4*)&bv[4] = *(const float4*)&Bs[kk][tx * 8 + 4];
#pragma unroll
            for (int i = 0; i < 8; i++)
#pragma unroll
                for (int j = 0; j < 8; j++) acc[i][j] += av[i] * bv[j];
        }
        __syncthreads();
    }
    const int t = m0 >> 8;                 // constant within this m-tile
    const int brow0 = (m0 & 255) + ty * 8;
#pragma unroll
    for (int jj = 0; jj < 8; jj++) {
        int j = n0 + tx * 8 + jj;
        float* orow = g_wx + (((size_t)(dd * TLEN + t)) * G4 + j) * BSZ + brow0;
        *(float4*)(orow)     = make_float4(acc[0][jj], acc[1][jj], acc[2][jj], acc[3][jj]);
        *(float4*)(orow + 4) = make_float4(acc[4][jj], acc[5][jj], acc[6][jj], acc[7][jj]);
    }
}

// ---------------- scan ----------------
struct SS {
    __half hT[8 * SKA];         // [n][k] fp16 acts
    __half uT[8 * SKA];
    __half xmT[8 * SKB];
    __half zsT[8 * SKB];
    __half yT[8 * SKB];
    __half dtw[DIN * 16];
    float  gates[3][8 * 256];   // f,g,o pre-acts [gate][n*256+j]
    float  cst[8 * 256];
    float  xdbl[8 * 64];
    float  bcs[8];
    float  bsum[G4];
    float  cw1[DIN], cb[DIN], dm[DIN], dtb[DIN];
};

__global__ __launch_bounds__(512) void scan_kernel(
    const __half* __restrict__ whhf,
    const float*  __restrict__ bih,
    const float*  __restrict__ bhh,
    const __half* __restrict__ inpf,
    const __half* __restrict__ outpf,
    const __half* __restrict__ xpf,
    const float*  __restrict__ conv_w,
    const float*  __restrict__ conv_b,
    const float*  __restrict__ dt_w,
    const float*  __restrict__ dt_b,
    const float*  __restrict__ Dm,
    float* __restrict__ outbuf,
    int first_layer)
{
    extern __shared__ char sraw[];
    SS* S = (SS*)sraw;
    const int tid  = threadIdx.x;
    const int w    = tid >> 5, lane = tid & 31;
    const int r    = lane >> 2, c2 = (lane & 3) * 2;
    const int nb   = lane >> 2;             // b-frag n
    const int dd   = blockIdx.x >> 5;
    const int b0g  = (blockIdx.x & 31) * 8;
    const uint4* whw = (const uint4*)(whhf + (size_t)dd * 16 * 64 * 256);

    // ---- init ----
#pragma unroll
    for (int i = 0; i < 2; i++) {
        int j = tid + i * 512;
        S->bsum[j] = bih[dd * G4 + j] + bhh[dd * G4 + j];
    }
    S->cw1[tid] = conv_w[tid * 2 + 1];
    S->cb[tid]  = conv_b[tid];
    S->dm[tid]  = Dm[tid];
    S->dtb[tid] = dt_b[tid];
#pragma unroll
    for (int i = 0; i < 16; i++) S->dtw[tid + i * 512] = __float2half(dt_w[tid + i * 512]);
#pragma unroll
    for (int i = 0; i < 4; i++) {
        int idx = tid + i * 512;           // 2048 = 8n x 256j
        int n = idx >> 8, j = idx & 255;
        if (first_layer) {
            S->hT[n * SKA + j] = __float2half(0.0f);
            S->cst[idx] = 0.0f;
        } else {
            S->hT[n * SKA + j] = __float2half(g_h[((size_t)dd * BSZ + b0g + n) * H + j]);
            S->cst[idx] = g_c[((size_t)dd * BSZ + b0g + n) * H + j];
        }
    }
    __syncthreads();

    for (int t = 0; t < TLEN; t++) {
        // ---- A: g = wx + h @ Whh^T ----
        float da[4][4];
        {
            const float* wxt = g_wx + ((size_t)(dd * TLEN + t)) * G4 * BSZ;
#pragma unroll
            for (int m = 0; m < 4; m++) {
                int j = (w * 4 + m) * 16 + r;
                const float* p = wxt + (size_t)j * BSZ + b0g + c2;
                float2 lo = *(const float2*)p;
                float2 hi = *(const float2*)(p + 8 * BSZ);
                da[m][0] = lo.x; da[m][1] = lo.y; da[m][2] = hi.x; da[m][3] = hi.y;
            }
        }
#pragma unroll 4
        for (int kt = 0; kt < 16; kt++) {
            unsigned bb0 = *(const unsigned*)&S->hT[nb * SKA + kt * 16 + c2];
            unsigned bb1 = *(const unsigned*)&S->hT[nb * SKA + kt * 16 + c2 + 8];
#pragma unroll
            for (int m = 0; m < 4; m++) {
                uint4 f = whw[(kt * 64 + w * 4 + m) * 32 + lane];
                mma16816(da[m], f.x, f.y, f.z, f.w, bb0, bb1);
            }
        }
        if (w < 4) {
#pragma unroll
            for (int m = 0; m < 4; m++) {
                int j = (w * 4 + m) * 16 + r;
                S->uT[(c2    ) * SKA + j    ] = __float2half(da[m][0]);
                S->uT[(c2 + 1) * SKA + j    ] = __float2half(da[m][1]);
                S->uT[(c2    ) * SKA + j + 8] = __float2half(da[m][2]);
                S->uT[(c2 + 1) * SKA + j + 8] = __float2half(da[m][3]);
            }
        } else {
            int gi = (w >> 2) - 1;
#pragma unroll
            for (int m = 0; m < 4; m++) {
                int jo = (((w * 4 + m) * 16 + r) & 255);
                S->gates[gi][(c2    ) * 256 + jo    ] = da[m][0];
                S->gates[gi][(c2 + 1) * 256 + jo    ] = da[m][1];
                S->gates[gi][(c2    ) * 256 + jo + 8] = da[m][2];
                S->gates[gi][(c2 + 1) * 256 + jo + 8] = da[m][3];
            }
        }
        __syncthreads();

        // ---- B: xz = u @ in_proj^T ----
#pragma unroll
        for (int m = 0; m < 4; m++)
#pragma unroll
            for (int q = 0; q < 4; q++) da[m][q] = 0.0f;
#pragma unroll 4
        for (int kt = 0; kt < 16; kt++) {
            unsigned bb0 = *(const unsigned*)&S->uT[nb * SKA + kt * 16 + c2];
            unsigned bb1 = *(const unsigned*)&S->uT[nb * SKA + kt * 16 + c2 + 8];
#pragma unroll
            for (int m = 0; m < 4; m++) {
                uint4 f = ((const uint4*)inpf)[(kt * 64 + w * 4 + m) * 32 + lane];
                mma16816(da[m], f.x, f.y, f.z, f.w, bb0, bb1);
            }
        }
        if (w < 8) {   // xm = silu(v*cw1 + cb)
#pragma unroll
            for (int m = 0; m < 4; m++) {
                int j = (w * 4 + m) * 16 + r;
#pragma unroll
                for (int q = 0; q < 4; q++) {
                    int jj = j + (q >> 1) * 8, n = c2 + (q & 1);
                    float pre = da[m][q] * S->cw1[jj] + S->cb[jj];
                    S->xmT[n * SKB + jj] = __float2half(pre * sigf(pre));
                }
            }
        } else {       // zs = silu(z)
#pragma unroll
            for (int m = 0; m < 4; m++) {
                int j = ((w - 8) * 4 + m) * 16 + r;
#pragma unroll
                for (int q = 0; q < 4; q++) {
                    int jj = j + (q >> 1) * 8, n = c2 + (q & 1);
                    float z = da[m][q];
                    S->zsT[n * SKB + jj] = __float2half(z * sigf(z));
                }
            }
        }
        __syncthreads();

        // ---- C: x_dbl = xm @ x_proj^T (M=48 pad 64) ----
        if (w < 4) {
            float dc[4] = {0, 0, 0, 0};
#pragma unroll 4
            for (int kt = 0; kt < 32; kt++) {
                unsigned bb0 = *(const unsigned*)&S->xmT[nb * SKB + kt * 16 + c2];
                unsigned bb1 = *(const unsigned*)&S->xmT[nb * SKB + kt * 16 + c2 + 8];
                uint4 f = ((const uint4*)xpf)[(kt * 4 + w) * 32 + lane];
                mma16816(dc, f.x, f.y, f.z, f.w, bb0, bb1);
            }
            int o = w * 16 + r;
            S->xdbl[(c2    ) * 64 + o    ] = dc[0];
            S->xdbl[(c2 + 1) * 64 + o    ] = dc[1];
            S->xdbl[(c2    ) * 64 + o + 8] = dc[2];
            S->xdbl[(c2 + 1) * 64 + o + 8] = dc[3];
        }
        __syncthreads();
        if (tid < 8) {
            float s = 0.0f;
#pragma unroll
            for (int ss = 0; ss < 16; ss++)
                s += S->xdbl[tid * 64 + 16 + ss] * S->xdbl[tid * 64 + 32 + ss];
            S->bcs[tid] = s;
        }
        __syncthreads();

        // ---- D: delta/softplus, y ----
        {
            int j = tid;
            float wr[16];
#pragma unroll
            for (int q = 0; q < 16; q++) wr[q] = __half2float(S->dtw[j * 16 + q]);
            float dtbj = S->dtb[j], dmj = S->dm[j];
#pragma unroll
            for (int n = 0; n < 8; n++) {
                float s = dtbj;
#pragma unroll
                for (int rr = 0; rr < 16; rr++) s += S->xdbl[n * 64 + rr] * wr[rr];
                float delta = fmaxf(s, 0.0f) + __logf(1.0f + __expf(-fabsf(s)));
                float y = (delta * S->bcs[n] + dmj) * __half2float(S->xmT[n * SKB + j])
                                                    * __half2float(S->zsT[n * SKB + j]);
                S->yT[n * SKB + j] = __float2half(y);
            }
        }
        __syncthreads();

        // ---- E: mamba_out = y @ out_proj^T ----
        float de[4] = {0, 0, 0, 0};
#pragma unroll 4
        for (int kt = 0; kt < 32; kt++) {
            unsigned bb0 = *(const unsigned*)&S->yT[nb * SKB + kt * 16 + c2];
            unsigned bb1 = *(const unsigned*)&S->yT[nb * SKB + kt * 16 + c2 + 8];
            uint4 f = ((const uint4*)outpf)[(kt * 16 + w) * 32 + lane];
            mma16816(de, f.x, f.y, f.z, f.w, bb0, bb1);
        }

        // ---- F: gates, state, output ----
        {
            int t_out = dd ? (TLEN - 1 - t) : t;
#pragma unroll
            for (int q = 0; q < 4; q++) {
                int jj = w * 16 + r + (q >> 1) * 8;
                int n  = c2 + (q & 1);
                int ix = n * 256 + jj;
                float iv = sigf(de[q] + S->bsum[jj]);
                float fv = sigf(S->gates[0][ix] + S->bsum[256 + jj]);
                float gv = tanhf(S->gates[1][ix] + S->bsum[512 + jj]);
                float ov = sigf(S->gates[2][ix] + S->bsum[768 + jj]);
                float cn = fv * S->cst[ix] + iv * gv;
                float hn = ov * tanhf(cn);
                S->cst[ix] = cn;
                S->hT[n * SKA + jj] = __float2half(hn);
                outbuf[((size_t)(b0g + n) * TLEN + t_out) * 512 + dd * 256 + jj] = hn;
            }
        }
        __syncthreads();
    }

#pragma unroll
    for (int i = 0; i < 4; i++) {
        int idx = tid + i * 512;
        int n = idx >> 8, j = idx & 255;
        g_h[((size_t)dd * BSZ + b0g + n) * H + j] = __half2float(S->hT[n * SKA + j]);
        g_c[((size_t)dd * BSZ + b0g + n) * H + j] = S->cst[idx];
    }
}

// =====================================================================
extern "C" void kernel_launch(void* const* d_in, const int* in_sizes, int n_in,
                              void* d_out, int out_size)
{
    (void)in_sizes; (void)n_in; (void)out_size;
    const float* x        = (const float*)d_in[0];
    const float* w_ih_l0  = (const float*)d_in[1];
    const float* w_hh_l0  = (const float*)d_in[2];
    const float* b_ih_l0  = (const float*)d_in[3];
    const float* b_hh_l0  = (const float*)d_in[4];
    const float* w_ih_l1  = (const float*)d_in[5];
    const float* w_hh_l1  = (const float*)d_in[6];
    const float* b_ih_l1  = (const float*)d_in[7];
    const float* b_hh_l1  = (const float*)d_in[8];
    const float* in_proj  = (const float*)d_in[9];
    const float* conv_w   = (const float*)d_in[10];
    const float* conv_b   = (const float*)d_in[11];
    const float* x_proj   = (const float*)d_in[12];
    const float* dt_w     = (const float*)d_in[13];
    const float* dt_b     = (const float*)d_in[14];
    const float* Dm       = (const float*)d_in[15];
    const float* out_proj = (const float*)d_in[16];
    float* out = (float*)d_out;

    static int inited = 0;
    int smem_bytes = (int)sizeof(SS);
    if (!inited) {
        cudaFuncSetAttribute(scan_kernel, cudaFuncAttributeMaxDynamicSharedMemorySize, smem_bytes);
        inited = 1;
    }

    float*  out0;  cudaGetSymbolAddress((void**)&out0,  g_out0);
    __half* whhf;  cudaGetSymbolAddress((void**)&whhf,  g_whhf);
    __half* inpf;  cudaGetSymbolAddress((void**)&inpf,  g_inpf);
    __half* outpf; cudaGetSymbolAddress((void**)&outpf, g_outpf);
    __half* xpf;   cudaGetSymbolAddress((void**)&xpf,   g_xpf);

    // shared (layer-independent) frag weights
    prepfrag<<<(16 * 64 * 256 + 255) / 256, 256>>>(in_proj, inpf, 64, 16, 1024);
    prepfrag<<<(32 * 16 * 256 + 255) / 256, 256>>>(out_proj, outpf, 16, 32, 256);
    prepfrag<<<(32 * 4 * 256 + 255) / 256, 256>>>(x_proj, xpf, 4, 32, 48);

    dim3 grid_wx(8, 256, 2);

    // ---- layer 0 ----
    prepfrag<<<(16 * 64 * 256 + 255) / 256, 256>>>(w_hh_l0, whhf, 64, 16, 1024);
    prepfrag<<<(16 * 64 * 256 + 255) / 256, 256>>>(w_hh_l0 + (size_t)G4 * H,
                                                   whhf + 16 * 64 * 256, 64, 16, 1024);
    wx_gemm_kernel<<<grid_wx, 256>>>(x, w_ih_l0, 128);
    scan_kernel<<<64, 512, smem_bytes>>>(whhf, b_ih_l0, b_hh_l0, inpf, outpf, xpf,
        conv_w, conv_b, dt_w, dt_b, Dm, out0, 1);

    // ---- layer 1 ----
    prepfrag<<<(16 * 64 * 256 + 255) / 256, 256>>>(w_hh_l1, whhf, 64, 16, 1024);
    prepfrag<<<(16 * 64 * 256 + 255) / 256, 256>>>(w_hh_l1 + (size_t)G4 * H,
                                                   whhf + 16 * 64 * 256, 64, 16, 1024);
    wx_gemm_kernel<<<grid_wx, 256>>>(out0, w_ih_l1, 512);
    scan_kernel<<<64, 512, smem_bytes>>>(whhf, b_ih_l1, b_hh_l1, inpf, outpf, xpf,
        conv_w, conv_b, dt_w, dt_b, Dm, out, 0);
}

// round 8
// speedup vs baseline: 3.5663x; 1.2461x over previous
#include <cuda_runtime.h>
#include <cuda_fp16.h>
#include <math.h>
#include <stdint.h>

#define H    256
#define BSZ  256
#define TLEN 128
#define G4   1024
#define DIN  512
#define SKA  264
#define SKB  520

__device__ float  g_wx[(size_t)2 * TLEN * G4 * BSZ];   // [d][t][j][b]
__device__ float  g_out0[(size_t)BSZ * TLEN * 512];
__device__ float  g_h[2 * BSZ * H];
__device__ float  g_c[2 * BSZ * H];
__device__ __half g_whhf[2 * 16 * 64 * 256];
__device__ __half g_inpf[16 * 64 * 256];
__device__ __half g_outpf[32 * 16 * 256];
__device__ __half g_xpf[32 * 4 * 256];
__device__ __half g_wihf0[2 * 8 * 64 * 256];    // layer0 w_ih frags (KT=8)
__device__ __half g_wihf1[2 * 32 * 64 * 256];   // layer1 w_ih frags (KT=32)
__device__ __half g_xbf[(size_t)TLEN * 32 * 4096];  // B-frag stream [t][kt][nt][lane][2xhalf2]

__device__ __forceinline__ float sigf(float x) { return 1.0f / (1.0f + __expf(-x)); }

__device__ __forceinline__ void mma16816(float d[4], unsigned a0, unsigned a1, unsigned a2,
                                         unsigned a3, unsigned b0, unsigned b1) {
    asm volatile(
        "mma.sync.aligned.m16n8k16.row.col.f32.f16.f16.f32 "
        "{%0,%1,%2,%3},{%4,%5,%6,%7},{%8,%9},{%0,%1,%2,%3};"
        : "+f"(d[0]), "+f"(d[1]), "+f"(d[2]), "+f"(d[3])
        : "r"(a0), "r"(a1), "r"(a2), "r"(a3), "r"(b0), "r"(b1));
}

// W[j][k] row-major -> A-frag-native: out[((kt*MT+mt)*32+lane)*8 + h]
__global__ void prepfrag(const float* __restrict__ W, __half* __restrict__ out,
                         int MT, int KT, int J)
{
    int idx = blockIdx.x * 256 + threadIdx.x;
    if (idx >= MT * KT * 256) return;
    int h = idx & 7, lane = (idx >> 3) & 31;
    int tile = idx >> 8;
    int mt = tile % MT, kt = tile / MT;
    int reg = h >> 1;
    int j = mt * 16 + (lane >> 2) + (reg & 1) * 8;
    int k = kt * 16 + (lane & 3) * 2 + (reg >> 1) * 8 + (h & 1);
    out[idx] = (j < J) ? __float2half(W[(size_t)j * (KT * 16) + k]) : __float2half(0.0f);
}

// X[b][t][K] fp32 -> B-frag-native fp16: half2 word widx = (((t*KT+kt)*32+nt)*32+lane)*2+which
__global__ void conv_bfrag(const float* __restrict__ X, __half* __restrict__ out,
                           int KT, int Kfull)
{
    int widx = blockIdx.x * 256 + threadIdx.x;
    if (widx >= TLEN * KT * 2048) return;
    int which = widx & 1;
    int lane  = (widx >> 1) & 31;
    int nt    = (widx >> 6) & 31;
    int kt    = (widx >> 11) % KT;
    int t     = (widx >> 11) / KT;
    int k = kt * 16 + which * 8 + (lane & 3) * 2;
    int b = nt * 8 + (lane >> 2);
    const float* p = X + ((size_t)b * TLEN + t) * Kfull + k;
    ((__half2*)out)[widx] = __floats2half2_rn(p[0], p[1]);
}

// ---------------- HMMA wx GEMM: g_wx[d][t][j][b] ----------------
__global__ __launch_bounds__(512) void wx_hmma(const __half* __restrict__ xbf,
                                               const __half* __restrict__ wf, int KT)
{
    const int d  = blockIdx.z;
    const int jb = blockIdx.y * 128;
    const int t  = blockIdx.x;
    const int ts = d ? (TLEN - 1 - t) : t;
    const int tid = threadIdx.x;
    const int w = tid >> 5, lane = tid & 31;
    const int mt = w >> 1, nt0 = (w & 1) * 16;
    const int r = lane >> 2, c2 = (lane & 3) * 2;
    const int mtg = (jb >> 4) + mt;

    const uint4* wfa = (const uint4*)(wf + (size_t)d * KT * 64 * 256);
    const uint2* bfr = (const uint2*)xbf;

    float acc[16][4];
#pragma unroll
    for (int q = 0; q < 16; q++)
#pragma unroll
        for (int i = 0; i < 4; i++) acc[q][i] = 0.0f;

    for (int kt = 0; kt < KT; kt++) {
        uint4 af = wfa[((size_t)kt * 64 + mtg) * 32 + lane];
        const uint2* bb = bfr + ((size_t)(ts * KT + kt)) * 1024 + nt0 * 32 + lane;
#pragma unroll
        for (int q = 0; q < 16; q++) {
            uint2 bv = bb[q * 32];
            mma16816(acc[q], af.x, af.y, af.z, af.w, bv.x, bv.y);
        }
    }

    const int j = jb + mt * 16 + r;
    float* obase = g_wx + (((size_t)(d * TLEN + t)) * G4 + j) * BSZ;
#pragma unroll
    for (int q = 0; q < 16; q++) {
        int b = (nt0 + q) * 8 + c2;
        *(float2*)(obase + b)             = make_float2(acc[q][0], acc[q][1]);
        *(float2*)(obase + 8 * BSZ + b)   = make_float2(acc[q][2], acc[q][3]);
    }
}

// ---------------- scan (unchanged from R6) ----------------
struct SS {
    __half hT[8 * SKA];
    __half uT[8 * SKA];
    __half xmT[8 * SKB];
    __half zsT[8 * SKB];
    __half yT[8 * SKB];
    __half dtw[DIN * 16];
    float  gates[3][8 * 256];
    float  cst[8 * 256];
    float  xdbl[8 * 64];
    float  bcs[8];
    float  bsum[G4];
    float  cw1[DIN], cb[DIN], dm[DIN], dtb[DIN];
};

__global__ __launch_bounds__(512) void scan_kernel(
    const __half* __restrict__ whhf,
    const float*  __restrict__ bih,
    const float*  __restrict__ bhh,
    const __half* __restrict__ inpf,
    const __half* __restrict__ outpf,
    const __half* __restrict__ xpf,
    const float*  __restrict__ conv_w,
    const float*  __restrict__ conv_b,
    const float*  __restrict__ dt_w,
    const float*  __restrict__ dt_b,
    const float*  __restrict__ Dm,
    float* __restrict__ outbuf,
    int first_layer)
{
    extern __shared__ char sraw[];
    SS* S = (SS*)sraw;
    const int tid  = threadIdx.x;
    const int w    = tid >> 5, lane = tid & 31;
    const int r    = lane >> 2, c2 = (lane & 3) * 2;
    const int nb   = lane >> 2;
    const int dd   = blockIdx.x >> 5;
    const int b0g  = (blockIdx.x & 31) * 8;
    const uint4* whw = (const uint4*)(whhf + (size_t)dd * 16 * 64 * 256);

#pragma unroll
    for (int i = 0; i < 2; i++) {
        int j = tid + i * 512;
        S->bsum[j] = bih[dd * G4 + j] + bhh[dd * G4 + j];
    }
    S->cw1[tid] = conv_w[tid * 2 + 1];
    S->cb[tid]  = conv_b[tid];
    S->dm[tid]  = Dm[tid];
    S->dtb[tid] = dt_b[tid];
#pragma unroll
    for (int i = 0; i < 16; i++) S->dtw[tid + i * 512] = __float2half(dt_w[tid + i * 512]);
#pragma unroll
    for (int i = 0; i < 4; i++) {
        int idx = tid + i * 512;
        int n = idx >> 8, j = idx & 255;
        if (first_layer) {
            S->hT[n * SKA + j] = __float2half(0.0f);
            S->cst[idx] = 0.0f;
        } else {
            S->hT[n * SKA + j] = __float2half(g_h[((size_t)dd * BSZ + b0g + n) * H + j]);
            S->cst[idx] = g_c[((size_t)dd * BSZ + b0g + n) * H + j];
        }
    }
    __syncthreads();

    for (int t = 0; t < TLEN; t++) {
        // ---- A: g = wx + h @ Whh^T ----
        float da[4][4];
        {
            const float* wxt = g_wx + ((size_t)(dd * TLEN + t)) * G4 * BSZ;
#pragma unroll
            for (int m = 0; m < 4; m++) {
                int j = (w * 4 + m) * 16 + r;
                const float* p = wxt + (size_t)j * BSZ + b0g + c2;
                float2 lo = *(const float2*)p;
                float2 hi = *(const float2*)(p + 8 * BSZ);
                da[m][0] = lo.x; da[m][1] = lo.y; da[m][2] = hi.x; da[m][3] = hi.y;
            }
        }
#pragma unroll 4
        for (int kt = 0; kt < 16; kt++) {
            unsigned bb0 = *(const unsigned*)&S->hT[nb * SKA + kt * 16 + c2];
            unsigned bb1 = *(const unsigned*)&S->hT[nb * SKA + kt * 16 + c2 + 8];
#pragma unroll
            for (int m = 0; m < 4; m++) {
                uint4 f = whw[(kt * 64 + w * 4 + m) * 32 + lane];
                mma16816(da[m], f.x, f.y, f.z, f.w, bb0, bb1);
            }
        }
        if (w < 4) {
#pragma unroll
            for (int m = 0; m < 4; m++) {
                int j = (w * 4 + m) * 16 + r;
                S->uT[(c2    ) * SKA + j    ] = __float2half(da[m][0]);
                S->uT[(c2 + 1) * SKA + j    ] = __float2half(da[m][1]);
                S->uT[(c2    ) * SKA + j + 8] = __float2half(da[m][2]);
                S->uT[(c2 + 1) * SKA + j + 8] = __float2half(da[m][3]);
            }
        } else {
            int gi = (w >> 2) - 1;
#pragma unroll
            for (int m = 0; m < 4; m++) {
                int jo = (((w * 4 + m) * 16 + r) & 255);
                S->gates[gi][(c2    ) * 256 + jo    ] = da[m][0];
                S->gates[gi][(c2 + 1) * 256 + jo    ] = da[m][1];
                S->gates[gi][(c2    ) * 256 + jo + 8] = da[m][2];
                S->gates[gi][(c2 + 1) * 256 + jo + 8] = da[m][3];
            }
        }
        __syncthreads();

        // ---- B: xz = u @ in_proj^T ----
#pragma unroll
        for (int m = 0; m < 4; m++)
#pragma unroll
            for (int q = 0; q < 4; q++) da[m][q] = 0.0f;
#pragma unroll 4
        for (int kt = 0; kt < 16; kt++) {
            unsigned bb0 = *(const unsigned*)&S->uT[nb * SKA + kt * 16 + c2];
            unsigned bb1 = *(const unsigned*)&S->uT[nb * SKA + kt * 16 + c2 + 8];
#pragma unroll
            for (int m = 0; m < 4; m++) {
                uint4 f = ((const uint4*)inpf)[(kt * 64 + w * 4 + m) * 32 + lane];
                mma16816(da[m], f.x, f.y, f.z, f.w, bb0, bb1);
            }
        }
        if (w < 8) {
#pragma unroll
            for (int m = 0; m < 4; m++) {
                int j = (w * 4 + m) * 16 + r;
#pragma unroll
                for (int q = 0; q < 4; q++) {
                    int jj = j + (q >> 1) * 8, n = c2 + (q & 1);
                    float pre = da[m][q] * S->cw1[jj] + S->cb[jj];
                    S->xmT[n * SKB + jj] = __float2half(pre * sigf(pre));
                }
            }
        } else {
#pragma unroll
            for (int m = 0; m < 4; m++) {
                int j = ((w - 8) * 4 + m) * 16 + r;
#pragma unroll
                for (int q = 0; q < 4; q++) {
                    int jj = j + (q >> 1) * 8, n = c2 + (q & 1);
                    float z = da[m][q];
                    S->zsT[n * SKB + jj] = __float2half(z * sigf(z));
                }
            }
        }
        __syncthreads();

        // ---- C: x_dbl = xm @ x_proj^T ----
        if (w < 4) {
            float dc[4] = {0, 0, 0, 0};
#pragma unroll 4
            for (int kt = 0; kt < 32; kt++) {
                unsigned bb0 = *(const unsigned*)&S->xmT[nb * SKB + kt * 16 + c2];
                unsigned bb1 = *(const unsigned*)&S->xmT[nb * SKB + kt * 16 + c2 + 8];
                uint4 f = ((const uint4*)xpf)[(kt * 4 + w) * 32 + lane];
                mma16816(dc, f.x, f.y, f.z, f.w, bb0, bb1);
            }
            int o = w * 16 + r;
            S->xdbl[(c2    ) * 64 + o    ] = dc[0];
            S->xdbl[(c2 + 1) * 64 + o    ] = dc[1];
            S->xdbl[(c2    ) * 64 + o + 8] = dc[2];
            S->xdbl[(c2 + 1) * 64 + o + 8] = dc[3];
        }
        __syncthreads();
        if (tid < 8) {
            float s = 0.0f;
#pragma unroll
            for (int ss = 0; ss < 16; ss++)
                s += S->xdbl[tid * 64 + 16 + ss] * S->xdbl[tid * 64 + 32 + ss];
            S->bcs[tid] = s;
        }
        __syncthreads();

        // ---- D: delta/softplus, y ----
        {
            int j = tid;
            float wr[16];
#pragma unroll
            for (int q = 0; q < 16; q++) wr[q] = __half2float(S->dtw[j * 16 + q]);
            float dtbj = S->dtb[j], dmj = S->dm[j];
#pragma unroll
            for (int n = 0; n < 8; n++) {
                float s = dtbj;
#pragma unroll
                for (int rr = 0; rr < 16; rr++) s += S->xdbl[n * 64 + rr] * wr[rr];
                float delta = fmaxf(s, 0.0f) + __logf(1.0f + __expf(-fabsf(s)));
                float y = (delta * S->bcs[n] + dmj) * __half2float(S->xmT[n * SKB + j])
                                                    * __half2float(S->zsT[n * SKB + j]);
                S->yT[n * SKB + j] = __float2half(y);
            }
        }
        __syncthreads();

        // ---- E: mamba_out = y @ out_proj^T ----
        float de[4] = {0, 0, 0, 0};
#pragma unroll 4
        for (int kt = 0; kt < 32; kt++) {
            unsigned bb0 = *(const unsigned*)&S->yT[nb * SKB + kt * 16 + c2];
            unsigned bb1 = *(const unsigned*)&S->yT[nb * SKB + kt * 16 + c2 + 8];
            uint4 f = ((const uint4*)outpf)[(kt * 16 + w) * 32 + lane];
            mma16816(de, f.x, f.y, f.z, f.w, bb0, bb1);
        }

        // ---- F: gates, state, output ----
        {
            int t_out = dd ? (TLEN - 1 - t) : t;
#pragma unroll
            for (int q = 0; q < 4; q++) {
                int jj = w * 16 + r + (q >> 1) * 8;
                int n  = c2 + (q & 1);
                int ix = n * 256 + jj;
                float iv = sigf(de[q] + S->bsum[jj]);
                float fv = sigf(S->gates[0][ix] + S->bsum[256 + jj]);
                float gv = tanhf(S->gates[1][ix] + S->bsum[512 + jj]);
                float ov = sigf(S->gates[2][ix] + S->bsum[768 + jj]);
                float cn = fv * S->cst[ix] + iv * gv;
                float hn = ov * tanhf(cn);
                S->cst[ix] = cn;
                S->hT[n * SKA + jj] = __float2half(hn);
                outbuf[((size_t)(b0g + n) * TLEN + t_out) * 512 + dd * 256 + jj] = hn;
            }
        }
        __syncthreads();
    }

#pragma unroll
    for (int i = 0; i < 4; i++) {
        int idx = tid + i * 512;
        int n = idx >> 8, j = idx & 255;
        g_h[((size_t)dd * BSZ + b0g + n) * H + j] = __half2float(S->hT[n * SKA + j]);
        g_c[((size_t)dd * BSZ + b0g + n) * H + j] = S->cst[idx];
    }
}

// =====================================================================
extern "C" void kernel_launch(void* const* d_in, const int* in_sizes, int n_in,
                              void* d_out, int out_size)
{
    (void)in_sizes; (void)n_in; (void)out_size;
    const float* x        = (const float*)d_in[0];
    const float* w_ih_l0  = (const float*)d_in[1];
    const float* w_hh_l0  = (const float*)d_in[2];
    const float* b_ih_l0  = (const float*)d_in[3];
    const float* b_hh_l0  = (const float*)d_in[4];
    const float* w_ih_l1  = (const float*)d_in[5];
    const float* w_hh_l1  = (const float*)d_in[6];
    const float* b_ih_l1  = (const float*)d_in[7];
    const float* b_hh_l1  = (const float*)d_in[8];
    const float* in_proj  = (const float*)d_in[9];
    const float* conv_w   = (const float*)d_in[10];
    const float* conv_b   = (const float*)d_in[11];
    const float* x_proj   = (const float*)d_in[12];
    const float* dt_w     = (const float*)d_in[13];
    const float* dt_b     = (const float*)d_in[14];
    const float* Dm       = (const float*)d_in[15];
    const float* out_proj = (const float*)d_in[16];
    float* out = (float*)d_out;

    static int inited = 0;
    int smem_bytes = (int)sizeof(SS);
    if (!inited) {
        cudaFuncSetAttribute(scan_kernel, cudaFuncAttributeMaxDynamicSharedMemorySize, smem_bytes);
        inited = 1;
    }

    float*  out0;   cudaGetSymbolAddress((void**)&out0,   g_out0);
    __half* whhf;   cudaGetSymbolAddress((void**)&whhf,   g_whhf);
    __half* inpf;   cudaGetSymbolAddress((void**)&inpf,   g_inpf);
    __half* outpf;  cudaGetSymbolAddress((void**)&outpf,  g_outpf);
    __half* xpf;    cudaGetSymbolAddress((void**)&xpf,    g_xpf);
    __half* wihf0;  cudaGetSymbolAddress((void**)&wihf0,  g_wihf0);
    __half* wihf1;  cudaGetSymbolAddress((void**)&wihf1,  g_wihf1);
    __half* xbf;    cudaGetSymbolAddress((void**)&xbf,    g_xbf);

    // layer-independent frag weights
    prepfrag<<<(16 * 64 * 256 + 255) / 256, 256>>>(in_proj, inpf, 64, 16, 1024);
    prepfrag<<<(32 * 16 * 256 + 255) / 256, 256>>>(out_proj, outpf, 16, 32, 256);
    prepfrag<<<(32 * 4 * 256 + 255) / 256, 256>>>(x_proj, xpf, 4, 32, 48);
    // w_ih frags (both layers, both dirs)
    prepfrag<<<(8 * 64 * 256 + 255) / 256, 256>>>(w_ih_l0, wihf0, 64, 8, 1024);
    prepfrag<<<(8 * 64 * 256 + 255) / 256, 256>>>(w_ih_l0 + (size_t)G4 * 128,
                                                  wihf0 + 8 * 64 * 256, 64, 8, 1024);
    prepfrag<<<(32 * 64 * 256 + 255) / 256, 256>>>(w_ih_l1, wihf1, 64, 32, 1024);
    prepfrag<<<(32 * 64 * 256 + 255) / 256, 256>>>(w_ih_l1 + (size_t)G4 * 512,
                                                   wihf1 + 32 * 64 * 256, 64, 32, 1024);

    // ---- layer 0 ----
    prepfrag<<<(16 * 64 * 256 + 255) / 256, 256>>>(w_hh_l0, whhf, 64, 16, 1024);
    prepfrag<<<(16 * 64 * 256 + 255) / 256, 256>>>(w_hh_l0 + (size_t)G4 * H,
                                                   whhf + 16 * 64 * 256, 64, 16, 1024);
    conv_bfrag<<<(TLEN * 8 * 2048 + 255) / 256, 256>>>(x, xbf, 8, 128);
    wx_hmma<<<dim3(TLEN, 8, 2), 512>>>(xbf, wihf0, 8);
    scan_kernel<<<64, 512, smem_bytes>>>(whhf, b_ih_l0, b_hh_l0, inpf, outpf, xpf,
        conv_w, conv_b, dt_w, dt_b, Dm, out0, 1);

    // ---- layer 1 ----
    prepfrag<<<(16 * 64 * 256 + 255) / 256, 256>>>(w_hh_l1, whhf, 64, 16, 1024);
    prepfrag<<<(16 * 64 * 256 + 255) / 256, 256>>>(w_hh_l1 + (size_t)G4 * H,
                                                   whhf + 16 * 64 * 256, 64, 16, 1024);
    conv_bfrag<<<(TLEN * 32 * 2048 + 255) / 256, 256>>>(out0, xbf, 32, 512);
    wx_hmma<<<dim3(TLEN, 8, 2), 512>>>(xbf, wihf1, 32);
    scan_kernel<<<64, 512, smem_bytes>>>(whhf, b_ih_l1, b_hh_l1, inpf, outpf, xpf,
        conv_w, conv_b, dt_w, dt_b, Dm, out, 0);
}